// round 1
// baseline (speedup 1.0000x reference)
#include <cuda_runtime.h>
#include <math.h>

#define NTOK   16384
#define DMODEL 1024
#define NHEAD  16
#define HDIM   64
#define NEXP   64
#define HE     1024      // NHEAD * NEXP
#define F1     256       // 4*E

// ---------------- device scratch (no allocations allowed) ----------------
__device__ float g_wqT [DMODEL * DMODEL];        // [d][r]  (wq column-major)
__device__ float g_wkvT[DMODEL * 2 * DMODEL];    // [k][n]  n<1024: wk row n, else wv
__device__ float g_w1T [DMODEL * F1];            // [k][n]
__device__ float g_woT [DMODEL * DMODEL];        // [j][dout]
__device__ float g_kv  [NEXP * 2 * DMODEL];      // [e][0:1024]=k, [1024:2048]=v
__device__ float g_kT  [DMODEL * NEXP];          // [h*64+hd][e]
__device__ float g_M   [DMODEL * HE];            // [d][he]
__device__ float g_c   [HE];
__device__ float g_P   [HE * DMODEL];            // [he][dout]
__device__ float g_attn[NTOK * HE];
__device__ float g_ao  [NTOK * DMODEL];
__device__ float g_h1  [NTOK * F1];

// ---------------- generic 32x32 transpose: dst[c][r] = src[r][c] ----------------
__global__ void transpose_kernel(const float* __restrict__ src, float* __restrict__ dst,
                                 int rows, int cols, int sstride) {
    __shared__ float tile[32][33];
    int c0 = blockIdx.x * 32;
    int r0 = blockIdx.y * 32;
    int tx = threadIdx.x, ty = threadIdx.y;   // 32 x 8
#pragma unroll
    for (int i = 0; i < 32; i += 8)
        tile[ty + i][tx] = src[(long)(r0 + ty + i) * sstride + c0 + tx];
    __syncthreads();
#pragma unroll
    for (int i = 0; i < 32; i += 8)
        dst[(long)(c0 + ty + i) * rows + r0 + tx] = tile[tx][ty + i];
}

// ---------------- SGEMM: C[M x N] = A[M x 1024] * B[1024 x N] + epilogue ----------------
// MODE 0: C = acc + bias[n]
// MODE 1: C = (acc + bias[n]) * 0.125f              (attention scores)
// MODE 2: C = gelu_exact(acc + bias[n])             (gate MLP hidden)
template<int MODE>
__global__ __launch_bounds__(256, 2)
void sgemm_k1024(const float* __restrict__ A, const float* __restrict__ B,
                 const float* __restrict__ bias, float* __restrict__ C,
                 int Arows, int Ncols) {
    const int K = 1024;
    __shared__ float As[2][8][128];
    __shared__ float Bs[2][8][128];

    int t = threadIdx.x;
    int rowBase = blockIdx.y * 128;
    int colBase = blockIdx.x * 128;

    int a_r = t >> 1;            // 0..127
    int a_k = (t & 1) * 4;       // 0 or 4
    int b_k = t >> 5;            // 0..7
    int b_n = (t & 31) * 4;      // 0..124

    int m0 = (t >> 4) * 8;       // 0..120
    int n0 = (t & 15) * 8;       // 0..120

    float acc[8][8];
#pragma unroll
    for (int i = 0; i < 8; i++)
#pragma unroll
        for (int j = 0; j < 8; j++) acc[i][j] = 0.f;

    const bool a_in = (rowBase + a_r) < Arows;
    const float* Aptr = A + (long)(rowBase + a_r) * K + a_k;
    const float* Bptr = B + (long)b_k * Ncols + colBase + b_n;

    float4 a_reg = make_float4(0.f, 0.f, 0.f, 0.f);
    float4 b_reg;
    if (a_in) a_reg = *(const float4*)(Aptr);
    b_reg = *(const float4*)(Bptr);

    As[0][a_k + 0][a_r] = a_reg.x;
    As[0][a_k + 1][a_r] = a_reg.y;
    As[0][a_k + 2][a_r] = a_reg.z;
    As[0][a_k + 3][a_r] = a_reg.w;
    *(float4*)&Bs[0][b_k][b_n] = b_reg;
    __syncthreads();

    const int KT = K / 8;   // 128
    for (int kt = 0; kt < KT; kt++) {
        int buf = kt & 1;
        if (kt + 1 < KT) {
            a_reg = make_float4(0.f, 0.f, 0.f, 0.f);
            if (a_in) a_reg = *(const float4*)(Aptr + (kt + 1) * 8);
            b_reg = *(const float4*)(Bptr + (long)(kt + 1) * 8 * Ncols);
        }
#pragma unroll
        for (int k = 0; k < 8; k++) {
            float a[8], b[8];
            *(float4*)&a[0] = *(float4*)&As[buf][k][m0];
            *(float4*)&a[4] = *(float4*)&As[buf][k][m0 + 4];
            *(float4*)&b[0] = *(float4*)&Bs[buf][k][n0];
            *(float4*)&b[4] = *(float4*)&Bs[buf][k][n0 + 4];
#pragma unroll
            for (int i = 0; i < 8; i++)
#pragma unroll
                for (int j = 0; j < 8; j++)
                    acc[i][j] = fmaf(a[i], b[j], acc[i][j]);
        }
        if (kt + 1 < KT) {
            int nb = buf ^ 1;
            As[nb][a_k + 0][a_r] = a_reg.x;
            As[nb][a_k + 1][a_r] = a_reg.y;
            As[nb][a_k + 2][a_r] = a_reg.z;
            As[nb][a_k + 3][a_r] = a_reg.w;
            *(float4*)&Bs[nb][b_k][b_n] = b_reg;
        }
        __syncthreads();
    }

#pragma unroll
    for (int i = 0; i < 8; i++) {
        int r = rowBase + m0 + i;
        if (r < Arows) {
            float o[8];
#pragma unroll
            for (int j = 0; j < 8; j++) {
                float v = acc[i][j] + bias[colBase + n0 + j];
                if (MODE == 1) v *= 0.125f;
                if (MODE == 2) v = 0.5f * v * (1.0f + erff(v * 0.70710678118654752f));
                o[j] = v;
            }
            *(float4*)&C[(long)r * Ncols + colBase + n0]     = *(float4*)&o[0];
            *(float4*)&C[(long)r * Ncols + colBase + n0 + 4] = *(float4*)&o[4];
        }
    }
}

// ---------------- M[d][he] = sum_hd wq[h*64+hd, d] * k[e, h*64+hd] ----------------
__global__ void build_M(const float* __restrict__ wqT, const float* __restrict__ kT,
                        float* __restrict__ M) {
    int d = blockIdx.x;
    __shared__ float wcol[DMODEL];
    for (int j = threadIdx.x; j < DMODEL; j += 256) wcol[j] = wqT[(long)d * DMODEL + j];
    __syncthreads();
    for (int he = threadIdx.x; he < HE; he += 256) {
        int h = he >> 6, e = he & 63;
        float s = 0.f;
#pragma unroll 8
        for (int hd = 0; hd < HDIM; hd++)
            s = fmaf(wcol[h * 64 + hd], kT[(h * 64 + hd) * NEXP + e], s);
        M[(long)d * HE + he] = s;
    }
}

// ---------------- c[he] = sum_hd bq[h*64+hd] * k[e, h*64+hd] ----------------
__global__ void build_c(const float* __restrict__ bq, const float* __restrict__ kT,
                        float* __restrict__ c) {
    int he = blockIdx.x * 256 + threadIdx.x;
    int h = he >> 6, e = he & 63;
    float s = 0.f;
#pragma unroll 8
    for (int hd = 0; hd < HDIM; hd++)
        s = fmaf(bq[h * 64 + hd], kT[(h * 64 + hd) * NEXP + e], s);
    c[he] = s;
}

// ---------------- P[he][dout] = sum_hd v[e, h*64+hd] * Wo[dout, h*64+hd] ----------------
__global__ void build_P(const float* __restrict__ kv, const float* __restrict__ woT,
                        float* __restrict__ P) {
    int he = blockIdx.x;
    int h = he >> 6, e = he & 63;
    __shared__ float v[HDIM];
    if (threadIdx.x < HDIM)
        v[threadIdx.x] = kv[(long)e * 2048 + 1024 + h * 64 + threadIdx.x];
    __syncthreads();
    for (int dout = threadIdx.x; dout < DMODEL; dout += 256) {
        float s = 0.f;
#pragma unroll 8
        for (int hd = 0; hd < HDIM; hd++)
            s = fmaf(v[hd], woT[(long)(h * 64 + hd) * DMODEL + dout], s);
        P[(long)he * DMODEL + dout] = s;
    }
}

// ---------------- per-(token,head) softmax over 64 experts, in place ----------------
__global__ void softmax64(float* __restrict__ data) {
    int row  = blockIdx.x * 8 + (threadIdx.x >> 5);
    int lane = threadIdx.x & 31;
    float* p = data + (long)row * 64;
    float v0 = p[lane], v1 = p[lane + 32];
    float m = fmaxf(v0, v1);
#pragma unroll
    for (int off = 16; off > 0; off >>= 1)
        m = fmaxf(m, __shfl_xor_sync(0xffffffffu, m, off));
    float e0 = expf(v0 - m), e1 = expf(v1 - m);
    float s = e0 + e1;
#pragma unroll
    for (int off = 16; off > 0; off >>= 1)
        s += __shfl_xor_sync(0xffffffffu, s, off);
    p[lane]      = e0 / s;
    p[lane + 32] = e1 / s;
}

// ---------------- gate logits + softmax + top-2 + weights ----------------
__global__ void gating_kernel(const float* __restrict__ h1, const float* __restrict__ w2,
                              const float* __restrict__ b2, float* __restrict__ out) {
    __shared__ float hrow[F1];
    __shared__ float lg[NEXP];
    int token = blockIdx.x;
    int t = threadIdx.x;   // 64 threads
#pragma unroll
    for (int j = t; j < F1; j += 64) hrow[j] = h1[(long)token * F1 + j];
    __syncthreads();
    float acc = 0.f;
#pragma unroll 8
    for (int j = 0; j < F1; j++) acc = fmaf(hrow[j], w2[t * F1 + j], acc);
    lg[t] = acc + b2[t];
    __syncthreads();
    if (t == 0) {
        int i1 = 0; float v1 = lg[0];
        for (int e = 1; e < NEXP; e++) if (lg[e] > v1) { v1 = lg[e]; i1 = e; }
        int i2 = -1; float v2 = -1e30f;
        for (int e = 0; e < NEXP; e++) if (e != i1 && lg[e] > v2) { v2 = lg[e]; i2 = e; }
        float s = 0.f;
        for (int e = 0; e < NEXP; e++) s += expf(lg[e] - v1);
        float p1 = 1.0f / s;
        float p2 = expf(v2 - v1) / s;
        float wsum = p1 + p2 + 1e-8f;
        out[token * 2 + 0] = (float)i1;
        out[token * 2 + 1] = (float)i2;
        out[NTOK * 2 + token * 2 + 0] = p1 / wsum;
        out[NTOK * 2 + token * 2 + 1] = p2 / wsum;
    }
}

// ---------------- launch ----------------
extern "C" void kernel_launch(void* const* d_in, const int* in_sizes, int n_in,
                              void* d_out, int out_size) {
    const float* x   = (const float*)d_in[0];
    const float* emb = (const float*)d_in[1];
    const float* ipw = (const float*)d_in[2];
    const float* ipb = (const float*)d_in[3];
    const float* opw = (const float*)d_in[4];
    const float* opb = (const float*)d_in[5];
    const float* gw1 = (const float*)d_in[6];
    const float* gb1 = (const float*)d_in[7];
    const float* gw2 = (const float*)d_in[8];
    const float* gb2 = (const float*)d_in[9];
    float* out = (float*)d_out;

    float *wqT, *wkvT, *w1T, *woT, *kv, *kT, *M, *c, *P, *attn, *ao, *h1;
    cudaGetSymbolAddress((void**)&wqT,  g_wqT);
    cudaGetSymbolAddress((void**)&wkvT, g_wkvT);
    cudaGetSymbolAddress((void**)&w1T,  g_w1T);
    cudaGetSymbolAddress((void**)&woT,  g_woT);
    cudaGetSymbolAddress((void**)&kv,   g_kv);
    cudaGetSymbolAddress((void**)&kT,   g_kT);
    cudaGetSymbolAddress((void**)&M,    g_M);
    cudaGetSymbolAddress((void**)&c,    g_c);
    cudaGetSymbolAddress((void**)&P,    g_P);
    cudaGetSymbolAddress((void**)&attn, g_attn);
    cudaGetSymbolAddress((void**)&ao,   g_ao);
    cudaGetSymbolAddress((void**)&h1,   g_h1);

    dim3 tb(32, 8);
    // weight transposes
    transpose_kernel<<<dim3(32, 32), tb>>>(ipw,               wqT,  1024, 1024, 1024);
    transpose_kernel<<<dim3(32, 64), tb>>>(ipw + 1024 * 1024, wkvT, 2048, 1024, 1024);
    transpose_kernel<<<dim3(32,  8), tb>>>(gw1,               w1T,   256, 1024, 1024);
    transpose_kernel<<<dim3(32, 32), tb>>>(opw,               woT,  1024, 1024, 1024);

    // k/v projections of the 64 expert embeddings: kv[e][0:2048]
    sgemm_k1024<0><<<dim3(16, 1), 256>>>(emb, wkvT, ipb + 1024, kv, 64, 2048);
    transpose_kernel<<<dim3(32, 2), tb>>>(kv, kT, 64, 1024, 2048);

    // fused score/output projection matrices
    build_M<<<1024, 256>>>(wqT, kT, M);
    build_c<<<4, 256>>>(ipb, kT, c);
    build_P<<<1024, 256>>>(kv, woT, P);

    // main pipeline
    sgemm_k1024<1><<<dim3(8, 128), 256>>>(x,    M,  c,   attn, NTOK, 1024);
    softmax64<<<NTOK * NHEAD / 8, 256>>>(attn);
    sgemm_k1024<0><<<dim3(8, 128), 256>>>(attn, P,  opb, ao,   NTOK, 1024);
    sgemm_k1024<2><<<dim3(2, 128), 256>>>(ao,   w1T, gb1, h1,  NTOK, 256);
    gating_kernel<<<NTOK, 64>>>(h1, gw2, gb2, out);
    (void)in_sizes; (void)n_in; (void)out_size;
}

// round 3
// speedup vs baseline: 1.5674x; 1.5674x over previous
#include <cuda_runtime.h>
#include <cuda_bf16.h>
#include <math.h>
#include <stdint.h>

#define NTOK   16384
#define DMODEL 1024
#define NEXP   64
#define F1     256

typedef __nv_bfloat16 bf16;

// ================= device scratch =================
__device__ float g_wqT [DMODEL * DMODEL];
__device__ float g_wkvT[DMODEL * 2 * DMODEL];
__device__ float g_woT [DMODEL * DMODEL];
__device__ float g_kv  [NEXP * 2 * DMODEL];
__device__ float g_kT  [DMODEL * NEXP];
__device__ float g_c   [DMODEL];
__device__ bf16  g_MTb [DMODEL * DMODEL];
__device__ bf16  g_MTs [DMODEL * DMODEL];
__device__ bf16  g_PTb [DMODEL * DMODEL];
__device__ bf16  g_PTs [DMODEL * DMODEL];
__device__ bf16  g_g1b [F1 * DMODEL];
__device__ bf16  g_g1s [F1 * DMODEL];
__device__ bf16  g_xb  [NTOK * DMODEL];   // x big   -> later ao big
__device__ bf16  g_xs  [NTOK * DMODEL];   // x small -> later ao small
__device__ bf16  g_ab  [NTOK * DMODEL];   // attn big
__device__ bf16  g_as  [NTOK * DMODEL];   // attn small
__device__ float g_h1  [NTOK * F1];

// ================= helpers =================
__device__ __forceinline__ uint32_t smem_u32(const void* p) {
    uint32_t a;
    asm("{ .reg .u64 t; cvta.to.shared.u64 t, %1; cvt.u32.u64 %0, t; }" : "=r"(a) : "l"(p));
    return a;
}
__device__ __forceinline__ void cp16(uint32_t dst, const void* src) {
    asm volatile("cp.async.cg.shared.global [%0], [%1], 16;" :: "r"(dst), "l"(src));
}
#define CP_COMMIT() asm volatile("cp.async.commit_group;" ::: "memory")
#define CP_WAIT1()  asm volatile("cp.async.wait_group 1;" ::: "memory")
#define CP_WAIT0()  asm volatile("cp.async.wait_group 0;" ::: "memory")

__device__ __forceinline__ void mma_bf16(float& d0, float& d1, float& d2, float& d3,
                                         uint32_t a0, uint32_t a1, uint32_t a2, uint32_t a3,
                                         uint32_t b0, uint32_t b1) {
    asm volatile(
        "mma.sync.aligned.m16n8k16.row.col.f32.bf16.bf16.f32 "
        "{%0,%1,%2,%3}, {%4,%5,%6,%7}, {%8,%9}, {%0,%1,%2,%3};"
        : "+f"(d0), "+f"(d1), "+f"(d2), "+f"(d3)
        : "r"(a0), "r"(a1), "r"(a2), "r"(a3), "r"(b0), "r"(b1));
}
__device__ __forceinline__ uint32_t pack_bf16(float lo, float hi) {
    uint16_t l = __bfloat16_as_ushort(__float2bfloat16_rn(lo));
    uint16_t h = __bfloat16_as_ushort(__float2bfloat16_rn(hi));
    return (uint32_t)l | ((uint32_t)h << 16);
}

// ================= generic transpose (fp32) =================
__global__ void transpose_kernel(const float* __restrict__ src, float* __restrict__ dst,
                                 int rows, int cols, int sstride) {
    __shared__ float tile[32][33];
    int c0 = blockIdx.x * 32, r0 = blockIdx.y * 32;
    int tx = threadIdx.x, ty = threadIdx.y;
#pragma unroll
    for (int i = 0; i < 32; i += 8)
        tile[ty + i][tx] = src[(long)(r0 + ty + i) * sstride + c0 + tx];
    __syncthreads();
#pragma unroll
    for (int i = 0; i < 32; i += 8)
        dst[(long)(c0 + ty + i) * rows + r0 + tx] = tile[tx][ty + i];
}

// ================= fp32 -> bf16 split =================
__global__ void split_kernel(const float4* __restrict__ src, uint2* __restrict__ big,
                             uint2* __restrict__ small, int n4) {
    int i = blockIdx.x * 256 + threadIdx.x;
    if (i < n4) {
        float4 v = src[i];
        float bx = __bfloat162float(__float2bfloat16_rn(v.x));
        float by = __bfloat162float(__float2bfloat16_rn(v.y));
        float bz = __bfloat162float(__float2bfloat16_rn(v.z));
        float bw = __bfloat162float(__float2bfloat16_rn(v.w));
        uint2 b, s;
        b.x = pack_bf16(bx, by); b.y = pack_bf16(bz, bw);
        s.x = pack_bf16(v.x - bx, v.y - by);
        s.y = pack_bf16(v.z - bz, v.w - bw);
        big[i] = b; small[i] = s;
    }
}

// ================= SIMT SGEMM (tiny kv projection only) =================
__global__ __launch_bounds__(256, 2)
void sgemm_k1024(const float* __restrict__ A, const float* __restrict__ B,
                 const float* __restrict__ bias, float* __restrict__ C,
                 int Arows, int Ncols) {
    const int K = 1024;
    __shared__ float Asm[2][8][128];
    __shared__ float Bsm[2][8][128];
    int t = threadIdx.x;
    int rowBase = blockIdx.y * 128, colBase = blockIdx.x * 128;
    int a_r = t >> 1, a_k = (t & 1) * 4;
    int b_k = t >> 5, b_n = (t & 31) * 4;
    int m0 = (t >> 4) * 8, n0 = (t & 15) * 8;
    float acc[8][8];
#pragma unroll
    for (int i = 0; i < 8; i++)
#pragma unroll
        for (int j = 0; j < 8; j++) acc[i][j] = 0.f;
    const bool a_in = (rowBase + a_r) < Arows;
    const float* Aptr = A + (long)(rowBase + a_r) * K + a_k;
    const float* Bptr = B + (long)b_k * Ncols + colBase + b_n;
    float4 a_reg = make_float4(0, 0, 0, 0), b_reg;
    if (a_in) a_reg = *(const float4*)(Aptr);
    b_reg = *(const float4*)(Bptr);
    Asm[0][a_k + 0][a_r] = a_reg.x; Asm[0][a_k + 1][a_r] = a_reg.y;
    Asm[0][a_k + 2][a_r] = a_reg.z; Asm[0][a_k + 3][a_r] = a_reg.w;
    *(float4*)&Bsm[0][b_k][b_n] = b_reg;
    __syncthreads();
    const int KT = K / 8;
    for (int kt = 0; kt < KT; kt++) {
        int buf = kt & 1;
        if (kt + 1 < KT) {
            a_reg = make_float4(0, 0, 0, 0);
            if (a_in) a_reg = *(const float4*)(Aptr + (kt + 1) * 8);
            b_reg = *(const float4*)(Bptr + (long)(kt + 1) * 8 * Ncols);
        }
#pragma unroll
        for (int k = 0; k < 8; k++) {
            float a[8], b[8];
            *(float4*)&a[0] = *(float4*)&Asm[buf][k][m0];
            *(float4*)&a[4] = *(float4*)&Asm[buf][k][m0 + 4];
            *(float4*)&b[0] = *(float4*)&Bsm[buf][k][n0];
            *(float4*)&b[4] = *(float4*)&Bsm[buf][k][n0 + 4];
#pragma unroll
            for (int i = 0; i < 8; i++)
#pragma unroll
                for (int j = 0; j < 8; j++) acc[i][j] = fmaf(a[i], b[j], acc[i][j]);
        }
        if (kt + 1 < KT) {
            int nb = buf ^ 1;
            Asm[nb][a_k + 0][a_r] = a_reg.x; Asm[nb][a_k + 1][a_r] = a_reg.y;
            Asm[nb][a_k + 2][a_r] = a_reg.z; Asm[nb][a_k + 3][a_r] = a_reg.w;
            *(float4*)&Bsm[nb][b_k][b_n] = b_reg;
        }
        __syncthreads();
    }
#pragma unroll
    for (int i = 0; i < 8; i++) {
        int r = rowBase + m0 + i;
        if (r < Arows) {
            float o[8];
#pragma unroll
            for (int j = 0; j < 8; j++) o[j] = acc[i][j] + bias[colBase + n0 + j];
            *(float4*)&C[(long)r * Ncols + colBase + n0]     = *(float4*)&o[0];
            *(float4*)&C[(long)r * Ncols + colBase + n0 + 4] = *(float4*)&o[4];
        }
    }
}

// ================= fused projection builders (output bf16 split, transposed) =================
__global__ void build_M(const float* __restrict__ wqT, const float* __restrict__ kT,
                        bf16* __restrict__ MTb, bf16* __restrict__ MTs) {
    int d = blockIdx.x;
    __shared__ float wcol[DMODEL];
    for (int j = threadIdx.x; j < DMODEL; j += 256) wcol[j] = wqT[(long)d * DMODEL + j];
    __syncthreads();
    for (int he = threadIdx.x; he < DMODEL; he += 256) {
        int h = he >> 6, e = he & 63;
        float s = 0.f;
#pragma unroll 8
        for (int hd = 0; hd < 64; hd++)
            s = fmaf(wcol[h * 64 + hd], kT[(h * 64 + hd) * NEXP + e], s);
        bf16 b = __float2bfloat16_rn(s);
        MTb[(long)he * DMODEL + d] = b;
        MTs[(long)he * DMODEL + d] = __float2bfloat16_rn(s - __bfloat162float(b));
    }
}

__global__ void build_c(const float* __restrict__ bq, const float* __restrict__ kT,
                        float* __restrict__ c) {
    int he = blockIdx.x * 256 + threadIdx.x;
    int h = he >> 6, e = he & 63;
    float s = 0.f;
#pragma unroll 8
    for (int hd = 0; hd < 64; hd++)
        s = fmaf(bq[h * 64 + hd], kT[(h * 64 + hd) * NEXP + e], s);
    c[he] = s;
}

__global__ void build_P(const float* __restrict__ kv, const float* __restrict__ woT,
                        bf16* __restrict__ PTb, bf16* __restrict__ PTs) {
    int he = blockIdx.x;
    int h = he >> 6, e = he & 63;
    __shared__ float v[64];
    if (threadIdx.x < 64)
        v[threadIdx.x] = kv[(long)e * 2048 + 1024 + h * 64 + threadIdx.x];
    __syncthreads();
    for (int dout = threadIdx.x; dout < DMODEL; dout += 256) {
        float s = 0.f;
#pragma unroll 8
        for (int hd = 0; hd < 64; hd++)
            s = fmaf(v[hd], woT[(long)(h * 64 + hd) * DMODEL + dout], s);
        bf16 b = __float2bfloat16_rn(s);
        PTb[(long)dout * DMODEL + he] = b;
        PTs[(long)dout * DMODEL + he] = __float2bfloat16_rn(s - __bfloat162float(b));
    }
}

// ================= bf16 3-split tensor-core GEMM (mma.sync) =================
// D[16384 x N] = (Ab+As)[16384 x 1024] * (Bb+Bs)[N x 1024]^T + bias  (drop As*Bs)
// MODE 0: bf16-split store to (outB, outS)
// MODE 1: *0.125, softmax over 64-col groups, bf16-split store
// MODE 2: exact GELU, fp32 store to outF
//
// CTA tile 128x128, k-chunk 32, 8 warps, warp tile 32x64 (wm=w>>1 rows, wn=w&1 cols).
// SMEM tile: 128 rows x 20 words (word = 2 bf16), data in words 0..15. Conflict-free.
#define ROWW 20
#define TILE_W (128 * ROWW)            // words per tile
#define STAGE_W (4 * TILE_W)           // Ab, As, Bb, Bs
#define SMEM_BYTES (2 * STAGE_W * 4)   // 81920

template<int MODE>
__global__ __launch_bounds__(256)
void tgemm(const bf16* __restrict__ Ab, const bf16* __restrict__ As,
           const bf16* __restrict__ Bb, const bf16* __restrict__ Bs,
           const float* __restrict__ bias,
           uint32_t* __restrict__ outB, uint32_t* __restrict__ outS,
           float* __restrict__ outF, int Ncols) {
    extern __shared__ uint32_t sm32[];
    uint32_t smu = smem_u32(sm32);

    const int t = threadIdx.x;
    const int w = t >> 5, lane = t & 31;
    const int wm = w >> 1, wn = w & 1;
    const int q = lane >> 2, c4 = lane & 3;

    const int rowBase = blockIdx.y * 128;
    const int colBase = blockIdx.x * 128;

    // ---- load pointers: thread t -> row t>>1, segs {t&1, (t&1)+2} (16B each)
    const int lr = t >> 1;
    const int ls = t & 1;
    const bf16* gAb = Ab + (long)(rowBase + lr) * 1024;
    const bf16* gAs = As + (long)(rowBase + lr) * 1024;
    const bf16* gBb = Bb + (long)(colBase + lr) * 1024;
    const bf16* gBs = Bs + (long)(colBase + lr) * 1024;
    const uint32_t dRow = smu + lr * (ROWW * 4);

    float acc[2][8][4];
#pragma unroll
    for (int mt = 0; mt < 2; mt++)
#pragma unroll
        for (int nt = 0; nt < 8; nt++)
#pragma unroll
            for (int i = 0; i < 4; i++) acc[mt][nt][i] = 0.f;

#define LOAD_STAGE(st, ck) do {                                                  \
    int kofs = (ck) * 32;                                                        \
    uint32_t sb = (st) * (STAGE_W * 4);                                          \
    _Pragma("unroll")                                                            \
    for (int j = 0; j < 2; j++) {                                                \
        int seg = ls * 2 + j;                                                    \
        cp16(dRow + sb + 0 * TILE_W * 4 + seg * 16, gAb + kofs + seg * 8);       \
        cp16(dRow + sb + 1 * TILE_W * 4 + seg * 16, gAs + kofs + seg * 8);       \
        cp16(dRow + sb + 2 * TILE_W * 4 + seg * 16, gBb + kofs + seg * 8);       \
        cp16(dRow + sb + 3 * TILE_W * 4 + seg * 16, gBs + kofs + seg * 8);       \
    }                                                                            \
} while (0)

    LOAD_STAGE(0, 0);
    CP_COMMIT();

    const int NC = 1024 / 32;
    for (int ck = 0; ck < NC; ck++) {
        int buf = ck & 1;
        if (ck + 1 < NC) {
            LOAD_STAGE(buf ^ 1, ck + 1);
            CP_COMMIT();
            CP_WAIT1();
        } else {
            CP_WAIT0();
        }
        __syncthreads();

        const uint32_t* sAb = sm32 + buf * STAGE_W;
        const uint32_t* sAs = sAb + TILE_W;
        const uint32_t* sBb = sAb + 2 * TILE_W;
        const uint32_t* sBs = sAb + 3 * TILE_W;

#pragma unroll
        for (int ks = 0; ks < 2; ks++) {
            uint32_t fab[2][4], fas[2][4];
#pragma unroll
            for (int mt = 0; mt < 2; mt++) {
                int base = (wm * 32 + mt * 16 + q) * ROWW + 8 * ks + c4;
                fab[mt][0] = sAb[base];           fab[mt][1] = sAb[base + 8 * ROWW];
                fab[mt][2] = sAb[base + 4];       fab[mt][3] = sAb[base + 8 * ROWW + 4];
                fas[mt][0] = sAs[base];           fas[mt][1] = sAs[base + 8 * ROWW];
                fas[mt][2] = sAs[base + 4];       fas[mt][3] = sAs[base + 8 * ROWW + 4];
            }
#pragma unroll
            for (int nt = 0; nt < 8; nt++) {
                int bb = (wn * 64 + nt * 8 + q) * ROWW + 8 * ks + c4;
                uint32_t bb0 = sBb[bb], bb1 = sBb[bb + 4];
                uint32_t bs0 = sBs[bb], bs1 = sBs[bb + 4];
#pragma unroll
                for (int mt = 0; mt < 2; mt++) {
                    float* d = acc[mt][nt];
                    mma_bf16(d[0], d[1], d[2], d[3],
                             fab[mt][0], fab[mt][1], fab[mt][2], fab[mt][3], bb0, bb1);
                    mma_bf16(d[0], d[1], d[2], d[3],
                             fab[mt][0], fab[mt][1], fab[mt][2], fab[mt][3], bs0, bs1);
                    mma_bf16(d[0], d[1], d[2], d[3],
                             fas[mt][0], fas[mt][1], fas[mt][2], fas[mt][3], bb0, bb1);
                }
            }
        }
        __syncthreads();
    }

    // ================= epilogue =================
    const int colB = colBase + wn * 64;
    float bv[16];
#pragma unroll
    for (int nt = 0; nt < 8; nt++) {
#pragma unroll
        for (int j = 0; j < 2; j++)
            bv[nt * 2 + j] = bias[colB + nt * 8 + 2 * c4 + j];
    }

#pragma unroll
    for (int mt = 0; mt < 2; mt++) {
#pragma unroll
        for (int h = 0; h < 2; h++) {
            int row = rowBase + wm * 32 + mt * 16 + q + h * 8;
            float v[16];
#pragma unroll
            for (int nt = 0; nt < 8; nt++) {
                v[nt * 2 + 0] = acc[mt][nt][2 * h + 0] + bv[nt * 2 + 0];
                v[nt * 2 + 1] = acc[mt][nt][2 * h + 1] + bv[nt * 2 + 1];
            }
            if (MODE == 1) {
#pragma unroll
                for (int i = 0; i < 16; i++) v[i] *= 0.125f;
                float m = v[0];
#pragma unroll
                for (int i = 1; i < 16; i++) m = fmaxf(m, v[i]);
                m = fmaxf(m, __shfl_xor_sync(0xffffffffu, m, 1));
                m = fmaxf(m, __shfl_xor_sync(0xffffffffu, m, 2));
                float s = 0.f;
#pragma unroll
                for (int i = 0; i < 16; i++) { v[i] = expf(v[i] - m); s += v[i]; }
                s += __shfl_xor_sync(0xffffffffu, s, 1);
                s += __shfl_xor_sync(0xffffffffu, s, 2);
                float inv = 1.f / s;
#pragma unroll
                for (int i = 0; i < 16; i++) v[i] *= inv;
            }
            if (MODE == 2) {
#pragma unroll
                for (int i = 0; i < 16; i++)
                    v[i] = 0.5f * v[i] * (1.0f + erff(v[i] * 0.70710678118654752f));
                float* op = outF + (long)row * Ncols + colB + 2 * c4;
#pragma unroll
                for (int nt = 0; nt < 8; nt++) {
                    op[nt * 8 + 0] = v[nt * 2 + 0];
                    op[nt * 8 + 1] = v[nt * 2 + 1];
                }
            } else {
                uint32_t* ob = outB + (long)row * (Ncols / 2) + (colB >> 1) + c4;
                uint32_t* os = outS + (long)row * (Ncols / 2) + (colB >> 1) + c4;
#pragma unroll
                for (int nt = 0; nt < 8; nt++) {
                    float v0 = v[nt * 2], v1 = v[nt * 2 + 1];
                    float b0 = __bfloat162float(__float2bfloat16_rn(v0));
                    float b1 = __bfloat162float(__float2bfloat16_rn(v1));
                    ob[nt * 4] = pack_bf16(b0, b1);
                    os[nt * 4] = pack_bf16(v0 - b0, v1 - b1);
                }
            }
        }
    }
#undef LOAD_STAGE
}

// ================= gating: logits + softmax + top-2 =================
__global__ void gating_kernel(const float* __restrict__ h1, const float* __restrict__ w2,
                              const float* __restrict__ b2, float* __restrict__ out) {
    __shared__ float hrow[4][F1];
    __shared__ float lg[4][NEXP];
    int t = threadIdx.x;
    int grp = t >> 6, e = t & 63;
    int token = blockIdx.x * 4 + grp;
    for (int j = e; j < F1; j += 64) hrow[grp][j] = h1[(long)token * F1 + j];
    __syncthreads();
    float acc = 0.f;
#pragma unroll 8
    for (int j = 0; j < F1; j++) acc = fmaf(hrow[grp][j], w2[e * F1 + j], acc);
    lg[grp][e] = acc + b2[e];
    __syncthreads();
    if (e == 0) {
        const float* L = lg[grp];
        int i1 = 0; float v1 = L[0];
        for (int k = 1; k < NEXP; k++) if (L[k] > v1) { v1 = L[k]; i1 = k; }
        int i2 = -1; float v2 = -1e30f;
        for (int k = 0; k < NEXP; k++) if (k != i1 && L[k] > v2) { v2 = L[k]; i2 = k; }
        float s = 0.f;
        for (int k = 0; k < NEXP; k++) s += expf(L[k] - v1);
        float p1 = 1.0f / s;
        float p2 = expf(v2 - v1) / s;
        float wsum = p1 + p2 + 1e-8f;
        out[token * 2 + 0] = (float)i1;
        out[token * 2 + 1] = (float)i2;
        out[NTOK * 2 + token * 2 + 0] = p1 / wsum;
        out[NTOK * 2 + token * 2 + 1] = p2 / wsum;
    }
}

// ================= launch =================
extern "C" void kernel_launch(void* const* d_in, const int* in_sizes, int n_in,
                              void* d_out, int out_size) {
    const float* x   = (const float*)d_in[0];
    const float* emb = (const float*)d_in[1];
    const float* ipw = (const float*)d_in[2];
    const float* ipb = (const float*)d_in[3];
    const float* opw = (const float*)d_in[4];
    const float* opb = (const float*)d_in[5];
    const float* gw1 = (const float*)d_in[6];
    const float* gb1 = (const float*)d_in[7];
    const float* gw2 = (const float*)d_in[8];
    const float* gb2 = (const float*)d_in[9];
    float* out = (float*)d_out;

    float *wqT, *wkvT, *woT, *kv, *kT, *c, *h1;
    bf16 *MTb, *MTs, *PTb, *PTs, *g1b, *g1s, *xb, *xs, *ab, *as_;
    cudaGetSymbolAddress((void**)&wqT,  g_wqT);
    cudaGetSymbolAddress((void**)&wkvT, g_wkvT);
    cudaGetSymbolAddress((void**)&woT,  g_woT);
    cudaGetSymbolAddress((void**)&kv,   g_kv);
    cudaGetSymbolAddress((void**)&kT,   g_kT);
    cudaGetSymbolAddress((void**)&c,    g_c);
    cudaGetSymbolAddress((void**)&MTb,  g_MTb);
    cudaGetSymbolAddress((void**)&MTs,  g_MTs);
    cudaGetSymbolAddress((void**)&PTb,  g_PTb);
    cudaGetSymbolAddress((void**)&PTs,  g_PTs);
    cudaGetSymbolAddress((void**)&g1b,  g_g1b);
    cudaGetSymbolAddress((void**)&g1s,  g_g1s);
    cudaGetSymbolAddress((void**)&xb,   g_xb);
    cudaGetSymbolAddress((void**)&xs,   g_xs);
    cudaGetSymbolAddress((void**)&ab,   g_ab);
    cudaGetSymbolAddress((void**)&as_,  g_as);
    cudaGetSymbolAddress((void**)&h1,   g_h1);

    cudaFuncSetAttribute(tgemm<0>, cudaFuncAttributeMaxDynamicSharedMemorySize, SMEM_BYTES);
    cudaFuncSetAttribute(tgemm<1>, cudaFuncAttributeMaxDynamicSharedMemorySize, SMEM_BYTES);
    cudaFuncSetAttribute(tgemm<2>, cudaFuncAttributeMaxDynamicSharedMemorySize, SMEM_BYTES);

    dim3 tb(32, 8);
    transpose_kernel<<<dim3(32, 32), tb>>>(ipw,               wqT,  1024, 1024, 1024);
    transpose_kernel<<<dim3(32, 64), tb>>>(ipw + 1024 * 1024, wkvT, 2048, 1024, 1024);
    transpose_kernel<<<dim3(32, 32), tb>>>(opw,               woT,  1024, 1024, 1024);

    split_kernel<<<(NTOK * DMODEL / 4 + 255) / 256, 256>>>(
        (const float4*)x, (uint2*)xb, (uint2*)xs, NTOK * DMODEL / 4);
    split_kernel<<<(F1 * DMODEL / 4 + 255) / 256, 256>>>(
        (const float4*)gw1, (uint2*)g1b, (uint2*)g1s, F1 * DMODEL / 4);

    sgemm_k1024<<<dim3(16, 1), 256>>>(emb, wkvT, ipb + 1024, kv, 64, 2048);
    transpose_kernel<<<dim3(32, 2), tb>>>(kv, kT, 64, 1024, 2048);

    build_M<<<1024, 256>>>(wqT, kT, MTb, MTs);
    build_c<<<4, 256>>>(ipb, kT, c);
    build_P<<<1024, 256>>>(kv, woT, PTb, PTs);

    // GEMM1: softmax((x@M + c)/8) -> attn (bf16 split)
    tgemm<1><<<dim3(8, 128), 256, SMEM_BYTES>>>(xb, xs, MTb, MTs, c,
                                                (uint32_t*)ab, (uint32_t*)as_, nullptr, 1024);
    // GEMM2: attn@P + opb -> ao (bf16 split), reusing x buffers
    tgemm<0><<<dim3(8, 128), 256, SMEM_BYTES>>>(ab, as_, PTb, PTs, opb,
                                                (uint32_t*)xb, (uint32_t*)xs, nullptr, 1024);
    // GEMM3: gelu(ao@gw1^T + gb1) -> h1 (fp32)
    tgemm<2><<<dim3(2, 128), 256, SMEM_BYTES>>>(xb, xs, g1b, g1s, gb1,
                                                nullptr, nullptr, h1, 256);

    gating_kernel<<<NTOK / 4, 256>>>(h1, gw2, gb2, out);
    (void)in_sizes; (void)n_in; (void)out_size;
}

// round 4
// speedup vs baseline: 1.5789x; 1.0074x over previous
#include <cuda_runtime.h>
#include <cuda_bf16.h>
#include <math.h>
#include <stdint.h>

#define NTOK   16384
#define DMODEL 1024
#define NEXP   64
#define F1     256

typedef __nv_bfloat16 bf16;

// ================= device scratch =================
__device__ float g_wqT [DMODEL * DMODEL];
__device__ float g_wkvT[DMODEL * 2 * DMODEL];
__device__ float g_woT [DMODEL * DMODEL];
__device__ float g_kv  [NEXP * 2 * DMODEL];
__device__ float g_kT  [DMODEL * NEXP];
__device__ float g_c   [DMODEL];
__device__ bf16  g_MTb [DMODEL * DMODEL];
__device__ bf16  g_MTs [DMODEL * DMODEL];
__device__ bf16  g_PTb [DMODEL * DMODEL];
__device__ bf16  g_PTs [DMODEL * DMODEL];
__device__ bf16  g_g1b [F1 * DMODEL];
__device__ bf16  g_g1s [F1 * DMODEL];
__device__ bf16  g_xb  [NTOK * DMODEL];   // x big   -> later ao big
__device__ bf16  g_xs  [NTOK * DMODEL];   // x small -> later ao small
__device__ bf16  g_ab  [NTOK * DMODEL];   // attn big
__device__ bf16  g_as  [NTOK * DMODEL];   // attn small
__device__ float g_h1  [NTOK * F1];

// ================= helpers =================
__device__ __forceinline__ uint32_t smem_u32(const void* p) {
    uint32_t a;
    asm("{ .reg .u64 t; cvta.to.shared.u64 t, %1; cvt.u32.u64 %0, t; }" : "=r"(a) : "l"(p));
    return a;
}
__device__ __forceinline__ void cp16(uint32_t dst, const void* src) {
    asm volatile("cp.async.cg.shared.global [%0], [%1], 16;" :: "r"(dst), "l"(src));
}
#define CP_COMMIT() asm volatile("cp.async.commit_group;" ::: "memory")
#define CP_WAIT1()  asm volatile("cp.async.wait_group 1;" ::: "memory")
#define CP_WAIT0()  asm volatile("cp.async.wait_group 0;" ::: "memory")

__device__ __forceinline__ void mma_bf16(float& d0, float& d1, float& d2, float& d3,
                                         uint32_t a0, uint32_t a1, uint32_t a2, uint32_t a3,
                                         uint32_t b0, uint32_t b1) {
    asm volatile(
        "mma.sync.aligned.m16n8k16.row.col.f32.bf16.bf16.f32 "
        "{%0,%1,%2,%3}, {%4,%5,%6,%7}, {%8,%9}, {%0,%1,%2,%3};"
        : "+f"(d0), "+f"(d1), "+f"(d2), "+f"(d3)
        : "r"(a0), "r"(a1), "r"(a2), "r"(a3), "r"(b0), "r"(b1));
}
__device__ __forceinline__ uint32_t pack_bf16(float lo, float hi) {
    uint16_t l = __bfloat16_as_ushort(__float2bfloat16_rn(lo));
    uint16_t h = __bfloat16_as_ushort(__float2bfloat16_rn(hi));
    return (uint32_t)l | ((uint32_t)h << 16);
}

// ================= fused transpose of wq, wkv, wo =================
__global__ void transpose_all(const float* __restrict__ ipw, const float* __restrict__ opw,
                              float* __restrict__ wqT, float* __restrict__ wkvT,
                              float* __restrict__ woT) {
    __shared__ float tile[32][33];
    int by = blockIdx.y;
    const float* src; float* dst; int rows; int byl;
    if (by < 32)      { src = ipw;                dst = wqT;  rows = 1024; byl = by; }
    else if (by < 96) { src = ipw + 1024 * 1024;  dst = wkvT; rows = 2048; byl = by - 32; }
    else              { src = opw;                dst = woT;  rows = 1024; byl = by - 96; }
    int c0 = blockIdx.x * 32, r0 = byl * 32;
    int tx = threadIdx.x, ty = threadIdx.y;
#pragma unroll
    for (int i = 0; i < 32; i += 8)
        tile[ty + i][tx] = src[(long)(r0 + ty + i) * 1024 + c0 + tx];
    __syncthreads();
#pragma unroll
    for (int i = 0; i < 32; i += 8)
        dst[(long)(c0 + ty + i) * rows + r0 + tx] = tile[tx][ty + i];
}

// ================= generic transpose (for kT) =================
__global__ void transpose_kernel(const float* __restrict__ src, float* __restrict__ dst,
                                 int rows, int cols, int sstride) {
    __shared__ float tile[32][33];
    int c0 = blockIdx.x * 32, r0 = blockIdx.y * 32;
    int tx = threadIdx.x, ty = threadIdx.y;
#pragma unroll
    for (int i = 0; i < 32; i += 8)
        tile[ty + i][tx] = src[(long)(r0 + ty + i) * sstride + c0 + tx];
    __syncthreads();
#pragma unroll
    for (int i = 0; i < 32; i += 8)
        dst[(long)(c0 + ty + i) * rows + r0 + tx] = tile[tx][ty + i];
}

// ================= fused fp32 -> bf16 split of x and gw1 =================
__global__ void split_all(const float4* __restrict__ x, uint2* __restrict__ xb,
                          uint2* __restrict__ xs, const float4* __restrict__ gw1,
                          uint2* __restrict__ g1b, uint2* __restrict__ g1s) {
    const float4* src; uint2* big; uint2* small; long i;
    if (blockIdx.x < 16384) {
        src = x; big = xb; small = xs;
        i = (long)blockIdx.x * 256 + threadIdx.x;
    } else {
        src = gw1; big = g1b; small = g1s;
        i = (long)(blockIdx.x - 16384) * 256 + threadIdx.x;
    }
    float4 v = src[i];
    float bx = __bfloat162float(__float2bfloat16_rn(v.x));
    float by = __bfloat162float(__float2bfloat16_rn(v.y));
    float bz = __bfloat162float(__float2bfloat16_rn(v.z));
    float bw = __bfloat162float(__float2bfloat16_rn(v.w));
    uint2 b, s;
    b.x = pack_bf16(bx, by); b.y = pack_bf16(bz, bw);
    s.x = pack_bf16(v.x - bx, v.y - by);
    s.y = pack_bf16(v.z - bz, v.w - bw);
    big[i] = b; small[i] = s;
}

// ================= SIMT SGEMM (tiny kv projection only) =================
__global__ __launch_bounds__(256, 2)
void sgemm_k1024(const float* __restrict__ A, const float* __restrict__ B,
                 const float* __restrict__ bias, float* __restrict__ C,
                 int Arows, int Ncols) {
    const int K = 1024;
    __shared__ float Asm[2][8][128];
    __shared__ float Bsm[2][8][128];
    int t = threadIdx.x;
    int rowBase = blockIdx.y * 128, colBase = blockIdx.x * 128;
    int a_r = t >> 1, a_k = (t & 1) * 4;
    int b_k = t >> 5, b_n = (t & 31) * 4;
    int m0 = (t >> 4) * 8, n0 = (t & 15) * 8;
    float acc[8][8];
#pragma unroll
    for (int i = 0; i < 8; i++)
#pragma unroll
        for (int j = 0; j < 8; j++) acc[i][j] = 0.f;
    const bool a_in = (rowBase + a_r) < Arows;
    const float* Aptr = A + (long)(rowBase + a_r) * K + a_k;
    const float* Bptr = B + (long)b_k * Ncols + colBase + b_n;
    float4 a_reg = make_float4(0, 0, 0, 0), b_reg;
    if (a_in) a_reg = *(const float4*)(Aptr);
    b_reg = *(const float4*)(Bptr);
    Asm[0][a_k + 0][a_r] = a_reg.x; Asm[0][a_k + 1][a_r] = a_reg.y;
    Asm[0][a_k + 2][a_r] = a_reg.z; Asm[0][a_k + 3][a_r] = a_reg.w;
    *(float4*)&Bsm[0][b_k][b_n] = b_reg;
    __syncthreads();
    const int KT = K / 8;
    for (int kt = 0; kt < KT; kt++) {
        int buf = kt & 1;
        if (kt + 1 < KT) {
            a_reg = make_float4(0, 0, 0, 0);
            if (a_in) a_reg = *(const float4*)(Aptr + (kt + 1) * 8);
            b_reg = *(const float4*)(Bptr + (long)(kt + 1) * 8 * Ncols);
        }
#pragma unroll
        for (int k = 0; k < 8; k++) {
            float a[8], b[8];
            *(float4*)&a[0] = *(float4*)&Asm[buf][k][m0];
            *(float4*)&a[4] = *(float4*)&Asm[buf][k][m0 + 4];
            *(float4*)&b[0] = *(float4*)&Bsm[buf][k][n0];
            *(float4*)&b[4] = *(float4*)&Bsm[buf][k][n0 + 4];
#pragma unroll
            for (int i = 0; i < 8; i++)
#pragma unroll
                for (int j = 0; j < 8; j++) acc[i][j] = fmaf(a[i], b[j], acc[i][j]);
        }
        if (kt + 1 < KT) {
            int nb = buf ^ 1;
            Asm[nb][a_k + 0][a_r] = a_reg.x; Asm[nb][a_k + 1][a_r] = a_reg.y;
            Asm[nb][a_k + 2][a_r] = a_reg.z; Asm[nb][a_k + 3][a_r] = a_reg.w;
            *(float4*)&Bsm[nb][b_k][b_n] = b_reg;
        }
        __syncthreads();
    }
#pragma unroll
    for (int i = 0; i < 8; i++) {
        int r = rowBase + m0 + i;
        if (r < Arows) {
            float o[8];
#pragma unroll
            for (int j = 0; j < 8; j++) o[j] = acc[i][j] + bias[colBase + n0 + j];
            *(float4*)&C[(long)r * Ncols + colBase + n0]     = *(float4*)&o[0];
            *(float4*)&C[(long)r * Ncols + colBase + n0 + 4] = *(float4*)&o[4];
        }
    }
}

// ================= fused M / P / c builder =================
// blocks 0..1023: M rows (d), 1024..2047: P rows (he), 2048+: c
__global__ void build_MCP(const float* __restrict__ wqT, const float* __restrict__ kT,
                          const float* __restrict__ kv, const float* __restrict__ woT,
                          const float* __restrict__ bq,
                          bf16* __restrict__ MTb, bf16* __restrict__ MTs,
                          bf16* __restrict__ PTb, bf16* __restrict__ PTs,
                          float* __restrict__ c) {
    __shared__ float buf[DMODEL];
    int bid = blockIdx.x;
    if (bid < 1024) {
        int d = bid;
        for (int j = threadIdx.x; j < DMODEL; j += 256) buf[j] = wqT[(long)d * DMODEL + j];
        __syncthreads();
        for (int he = threadIdx.x; he < DMODEL; he += 256) {
            int h = he >> 6, e = he & 63;
            float s = 0.f;
#pragma unroll 8
            for (int hd = 0; hd < 64; hd++)
                s = fmaf(buf[h * 64 + hd], kT[(h * 64 + hd) * NEXP + e], s);
            bf16 b = __float2bfloat16_rn(s);
            MTb[(long)he * DMODEL + d] = b;
            MTs[(long)he * DMODEL + d] = __float2bfloat16_rn(s - __bfloat162float(b));
        }
    } else if (bid < 2048) {
        int he = bid - 1024;
        int h = he >> 6, e = he & 63;
        if (threadIdx.x < 64)
            buf[threadIdx.x] = kv[(long)e * 2048 + 1024 + h * 64 + threadIdx.x];
        __syncthreads();
        for (int dout = threadIdx.x; dout < DMODEL; dout += 256) {
            float s = 0.f;
#pragma unroll 8
            for (int hd = 0; hd < 64; hd++)
                s = fmaf(buf[hd], woT[(long)(h * 64 + hd) * DMODEL + dout], s);
            bf16 b = __float2bfloat16_rn(s);
            PTb[(long)dout * DMODEL + he] = b;
            PTs[(long)dout * DMODEL + he] = __float2bfloat16_rn(s - __bfloat162float(b));
        }
    } else {
        for (int he = threadIdx.x; he < DMODEL; he += 256) {
            int h = he >> 6, e = he & 63;
            float s = 0.f;
#pragma unroll 8
            for (int hd = 0; hd < 64; hd++)
                s = fmaf(bq[h * 64 + hd], kT[(h * 64 + hd) * NEXP + e], s);
            c[he] = s;
        }
    }
}

// ================= bf16 3-split tensor-core GEMM (mma.sync) =================
// D[16384 x N] = (Ab+As)[16384 x 1024] * (Bb+Bs)[N x 1024]^T + bias  (drop As*Bs)
// MODE 0: bf16-split store   MODE 1: *0.125 + 64-group softmax + split   MODE 2: GELU fp32
// CTA 128x128, k-chunk 32, 8 warps, warp tile 32x64. Term-major MMA order for ILP.
#define ROWW 20
#define TILE_W (128 * ROWW)
#define STAGE_W (4 * TILE_W)
#define SMEM_BYTES (2 * STAGE_W * 4)   // 81920

template<int MODE>
__global__ __launch_bounds__(256)
void tgemm(const bf16* __restrict__ Ab, const bf16* __restrict__ As,
           const bf16* __restrict__ Bb, const bf16* __restrict__ Bs,
           const float* __restrict__ bias,
           uint32_t* __restrict__ outB, uint32_t* __restrict__ outS,
           float* __restrict__ outF, int Ncols) {
    extern __shared__ uint32_t sm32[];
    uint32_t smu = smem_u32(sm32);

    const int t = threadIdx.x;
    const int w = t >> 5, lane = t & 31;
    const int wm = w >> 1, wn = w & 1;
    const int q = lane >> 2, c4 = lane & 3;

    const int rowBase = blockIdx.y * 128;
    const int colBase = blockIdx.x * 128;

    const int lr = t >> 1;
    const int ls = t & 1;
    const bf16* gAb = Ab + (long)(rowBase + lr) * 1024;
    const bf16* gAs = As + (long)(rowBase + lr) * 1024;
    const bf16* gBb = Bb + (long)(colBase + lr) * 1024;
    const bf16* gBs = Bs + (long)(colBase + lr) * 1024;
    const uint32_t dRow = smu + lr * (ROWW * 4);

    float acc[2][8][4];
#pragma unroll
    for (int mt = 0; mt < 2; mt++)
#pragma unroll
        for (int nt = 0; nt < 8; nt++)
#pragma unroll
            for (int i = 0; i < 4; i++) acc[mt][nt][i] = 0.f;

#define LOAD_STAGE(st, ck) do {                                                  \
    int kofs = (ck) * 32;                                                        \
    uint32_t sb = (st) * (STAGE_W * 4);                                          \
    _Pragma("unroll")                                                            \
    for (int j = 0; j < 2; j++) {                                                \
        int seg = ls * 2 + j;                                                    \
        cp16(dRow + sb + 0 * TILE_W * 4 + seg * 16, gAb + kofs + seg * 8);       \
        cp16(dRow + sb + 1 * TILE_W * 4 + seg * 16, gAs + kofs + seg * 8);       \
        cp16(dRow + sb + 2 * TILE_W * 4 + seg * 16, gBb + kofs + seg * 8);       \
        cp16(dRow + sb + 3 * TILE_W * 4 + seg * 16, gBs + kofs + seg * 8);       \
    }                                                                            \
} while (0)

    LOAD_STAGE(0, 0);
    CP_COMMIT();

    const int NC = 1024 / 32;
    for (int ck = 0; ck < NC; ck++) {
        int buf = ck & 1;
        if (ck + 1 < NC) {
            LOAD_STAGE(buf ^ 1, ck + 1);
            CP_COMMIT();
            CP_WAIT1();
        } else {
            CP_WAIT0();
        }
        __syncthreads();

        const uint32_t* sAb = sm32 + buf * STAGE_W;
        const uint32_t* sAs = sAb + TILE_W;
        const uint32_t* sBb = sAb + 2 * TILE_W;
        const uint32_t* sBs = sAb + 3 * TILE_W;

#pragma unroll
        for (int ks = 0; ks < 2; ks++) {
            uint32_t fab[2][4], fas[2][4], fbb[8][2], fbs[8][2];
#pragma unroll
            for (int mt = 0; mt < 2; mt++) {
                int base = (wm * 32 + mt * 16 + q) * ROWW + 8 * ks + c4;
                fab[mt][0] = sAb[base];           fab[mt][1] = sAb[base + 8 * ROWW];
                fab[mt][2] = sAb[base + 4];       fab[mt][3] = sAb[base + 8 * ROWW + 4];
                fas[mt][0] = sAs[base];           fas[mt][1] = sAs[base + 8 * ROWW];
                fas[mt][2] = sAs[base + 4];       fas[mt][3] = sAs[base + 8 * ROWW + 4];
            }
#pragma unroll
            for (int nt = 0; nt < 8; nt++) {
                int bb = (wn * 64 + nt * 8 + q) * ROWW + 8 * ks + c4;
                fbb[nt][0] = sBb[bb]; fbb[nt][1] = sBb[bb + 4];
                fbs[nt][0] = sBs[bb]; fbs[nt][1] = sBs[bb + 4];
            }
            // term-major issue order: 16 independent MMAs between same-acc reuse
#pragma unroll
            for (int nt = 0; nt < 8; nt++)
#pragma unroll
                for (int mt = 0; mt < 2; mt++)
                    mma_bf16(acc[mt][nt][0], acc[mt][nt][1], acc[mt][nt][2], acc[mt][nt][3],
                             fab[mt][0], fab[mt][1], fab[mt][2], fab[mt][3],
                             fbb[nt][0], fbb[nt][1]);
#pragma unroll
            for (int nt = 0; nt < 8; nt++)
#pragma unroll
                for (int mt = 0; mt < 2; mt++)
                    mma_bf16(acc[mt][nt][0], acc[mt][nt][1], acc[mt][nt][2], acc[mt][nt][3],
                             fab[mt][0], fab[mt][1], fab[mt][2], fab[mt][3],
                             fbs[nt][0], fbs[nt][1]);
#pragma unroll
            for (int nt = 0; nt < 8; nt++)
#pragma unroll
                for (int mt = 0; mt < 2; mt++)
                    mma_bf16(acc[mt][nt][0], acc[mt][nt][1], acc[mt][nt][2], acc[mt][nt][3],
                             fas[mt][0], fas[mt][1], fas[mt][2], fas[mt][3],
                             fbb[nt][0], fbb[nt][1]);
        }
        __syncthreads();
    }

    // ================= epilogue =================
    const int colB = colBase + wn * 64;
    float bv[16];
#pragma unroll
    for (int nt = 0; nt < 8; nt++) {
#pragma unroll
        for (int j = 0; j < 2; j++)
            bv[nt * 2 + j] = bias[colB + nt * 8 + 2 * c4 + j];
    }

#pragma unroll
    for (int mt = 0; mt < 2; mt++) {
#pragma unroll
        for (int h = 0; h < 2; h++) {
            int row = rowBase + wm * 32 + mt * 16 + q + h * 8;
            float v[16];
#pragma unroll
            for (int nt = 0; nt < 8; nt++) {
                v[nt * 2 + 0] = acc[mt][nt][2 * h + 0] + bv[nt * 2 + 0];
                v[nt * 2 + 1] = acc[mt][nt][2 * h + 1] + bv[nt * 2 + 1];
            }
            if (MODE == 1) {
#pragma unroll
                for (int i = 0; i < 16; i++) v[i] *= 0.125f;
                float m = v[0];
#pragma unroll
                for (int i = 1; i < 16; i++) m = fmaxf(m, v[i]);
                m = fmaxf(m, __shfl_xor_sync(0xffffffffu, m, 1));
                m = fmaxf(m, __shfl_xor_sync(0xffffffffu, m, 2));
                float s = 0.f;
#pragma unroll
                for (int i = 0; i < 16; i++) { v[i] = expf(v[i] - m); s += v[i]; }
                s += __shfl_xor_sync(0xffffffffu, s, 1);
                s += __shfl_xor_sync(0xffffffffu, s, 2);
                float inv = 1.f / s;
#pragma unroll
                for (int i = 0; i < 16; i++) v[i] *= inv;
            }
            if (MODE == 2) {
#pragma unroll
                for (int i = 0; i < 16; i++)
                    v[i] = 0.5f * v[i] * (1.0f + erff(v[i] * 0.70710678118654752f));
                float* op = outF + (long)row * Ncols + colB + 2 * c4;
#pragma unroll
                for (int nt = 0; nt < 8; nt++) {
                    op[nt * 8 + 0] = v[nt * 2 + 0];
                    op[nt * 8 + 1] = v[nt * 2 + 1];
                }
            } else {
                uint32_t* ob = outB + (long)row * (Ncols / 2) + (colB >> 1) + c4;
                uint32_t* os = outS + (long)row * (Ncols / 2) + (colB >> 1) + c4;
#pragma unroll
                for (int nt = 0; nt < 8; nt++) {
                    float v0 = v[nt * 2], v1 = v[nt * 2 + 1];
                    float b0 = __bfloat162float(__float2bfloat16_rn(v0));
                    float b1 = __bfloat162float(__float2bfloat16_rn(v1));
                    ob[nt * 4] = pack_bf16(b0, b1);
                    os[nt * 4] = pack_bf16(v0 - b0, v1 - b1);
                }
            }
        }
    }
#undef LOAD_STAGE
}

// ================= gating: logits + softmax + top-2 =================
__global__ void gating_kernel(const float* __restrict__ h1, const float* __restrict__ w2,
                              const float* __restrict__ b2, float* __restrict__ out) {
    __shared__ float hrow[4][F1];
    __shared__ float lg[4][NEXP];
    int t = threadIdx.x;
    int grp = t >> 6, e = t & 63;
    int token = blockIdx.x * 4 + grp;
    for (int j = e; j < F1; j += 64) hrow[grp][j] = h1[(long)token * F1 + j];
    __syncthreads();
    float acc = 0.f;
#pragma unroll 8
    for (int j = 0; j < F1; j++) acc = fmaf(hrow[grp][j], w2[e * F1 + j], acc);
    lg[grp][e] = acc + b2[e];
    __syncthreads();
    if (e == 0) {
        const float* L = lg[grp];
        int i1 = 0; float v1 = L[0];
        for (int k = 1; k < NEXP; k++) if (L[k] > v1) { v1 = L[k]; i1 = k; }
        int i2 = -1; float v2 = -1e30f;
        for (int k = 0; k < NEXP; k++) if (k != i1 && L[k] > v2) { v2 = L[k]; i2 = k; }
        float s = 0.f;
        for (int k = 0; k < NEXP; k++) s += expf(L[k] - v1);
        float p1 = 1.0f / s;
        float p2 = expf(v2 - v1) / s;
        float wsum = p1 + p2 + 1e-8f;
        out[token * 2 + 0] = (float)i1;
        out[token * 2 + 1] = (float)i2;
        out[NTOK * 2 + token * 2 + 0] = p1 / wsum;
        out[NTOK * 2 + token * 2 + 1] = p2 / wsum;
    }
}

// ================= launch =================
extern "C" void kernel_launch(void* const* d_in, const int* in_sizes, int n_in,
                              void* d_out, int out_size) {
    const float* x   = (const float*)d_in[0];
    const float* emb = (const float*)d_in[1];
    const float* ipw = (const float*)d_in[2];
    const float* ipb = (const float*)d_in[3];
    const float* opw = (const float*)d_in[4];
    const float* opb = (const float*)d_in[5];
    const float* gw1 = (const float*)d_in[6];
    const float* gb1 = (const float*)d_in[7];
    const float* gw2 = (const float*)d_in[8];
    const float* gb2 = (const float*)d_in[9];
    float* out = (float*)d_out;

    float *wqT, *wkvT, *woT, *kv, *kT, *c, *h1;
    bf16 *MTb, *MTs, *PTb, *PTs, *g1b, *g1s, *xb, *xs, *ab, *as_;
    cudaGetSymbolAddress((void**)&wqT,  g_wqT);
    cudaGetSymbolAddress((void**)&wkvT, g_wkvT);
    cudaGetSymbolAddress((void**)&woT,  g_woT);
    cudaGetSymbolAddress((void**)&kv,   g_kv);
    cudaGetSymbolAddress((void**)&kT,   g_kT);
    cudaGetSymbolAddress((void**)&c,    g_c);
    cudaGetSymbolAddress((void**)&MTb,  g_MTb);
    cudaGetSymbolAddress((void**)&MTs,  g_MTs);
    cudaGetSymbolAddress((void**)&PTb,  g_PTb);
    cudaGetSymbolAddress((void**)&PTs,  g_PTs);
    cudaGetSymbolAddress((void**)&g1b,  g_g1b);
    cudaGetSymbolAddress((void**)&g1s,  g_g1s);
    cudaGetSymbolAddress((void**)&xb,   g_xb);
    cudaGetSymbolAddress((void**)&xs,   g_xs);
    cudaGetSymbolAddress((void**)&ab,   g_ab);
    cudaGetSymbolAddress((void**)&as_,  g_as);
    cudaGetSymbolAddress((void**)&h1,   g_h1);

    cudaFuncSetAttribute(tgemm<0>, cudaFuncAttributeMaxDynamicSharedMemorySize, SMEM_BYTES);
    cudaFuncSetAttribute(tgemm<1>, cudaFuncAttributeMaxDynamicSharedMemorySize, SMEM_BYTES);
    cudaFuncSetAttribute(tgemm<2>, cudaFuncAttributeMaxDynamicSharedMemorySize, SMEM_BYTES);

    dim3 tb(32, 8);
    // L0
    transpose_all<<<dim3(32, 128), tb>>>(ipw, opw, wqT, wkvT, woT);
    // L1
    split_all<<<16384 + 256, 256>>>((const float4*)x, (uint2*)xb, (uint2*)xs,
                                    (const float4*)gw1, (uint2*)g1b, (uint2*)g1s);
    // L2
    sgemm_k1024<<<dim3(16, 1), 256>>>(emb, wkvT, ipb + 1024, kv, 64, 2048);
    // L3
    transpose_kernel<<<dim3(32, 2), tb>>>(kv, kT, 64, 1024, 2048);
    // L4
    build_MCP<<<2049, 256>>>(wqT, kT, kv, woT, ipb, MTb, MTs, PTb, PTs, c);

    // L5: GEMM1 softmax((x@M + c)/8) -> attn (bf16 split)   [ncu profiles this]
    tgemm<1><<<dim3(8, 128), 256, SMEM_BYTES>>>(xb, xs, MTb, MTs, c,
                                                (uint32_t*)ab, (uint32_t*)as_, nullptr, 1024);
    // L6: GEMM2 attn@P + opb -> ao (bf16 split), reusing x buffers
    tgemm<0><<<dim3(8, 128), 256, SMEM_BYTES>>>(ab, as_, PTb, PTs, opb,
                                                (uint32_t*)xb, (uint32_t*)xs, nullptr, 1024);
    // L7: GEMM3 gelu(ao@gw1^T + gb1) -> h1 (fp32)
    tgemm<2><<<dim3(2, 128), 256, SMEM_BYTES>>>(xb, xs, g1b, g1s, gb1,
                                                nullptr, nullptr, h1, 256);
    // L8
    gating_kernel<<<NTOK / 4, 256>>>(h1, gw2, gb2, out);
    (void)in_sizes; (void)n_in; (void)out_size;
}

// round 5
// speedup vs baseline: 1.7339x; 1.0982x over previous
#include <cuda_runtime.h>
#include <cuda_bf16.h>
#include <math.h>
#include <stdint.h>

#define NTOK   16384
#define DMODEL 1024
#define NEXP   64
#define F1     256

typedef __nv_bfloat16 bf16;

// ================= device scratch =================
__device__ float g_wkvT[DMODEL * 2 * DMODEL];   // [k][n]
__device__ float g_kv  [NEXP * 2 * DMODEL];     // [e][0:1024]=k, [1024:2048]=v
__device__ float g_c   [DMODEL];                // score bias per (h,e)
__device__ float g_W2gT[F1 * DMODEL];           // [j][i] = sum_d gw1[j,d]*wo[d,i]
__device__ float g_c2  [F1];                    // opb@gw1^T + gb1
__device__ bf16  g_MTb [DMODEL * DMODEL];       // [he][d]
__device__ bf16  g_MTs [DMODEL * DMODEL];
__device__ bf16  g_Gtb [F1 * DMODEL];           // [j][he]
__device__ bf16  g_Gts [F1 * DMODEL];
__device__ bf16  g_xb  [NTOK * DMODEL];
__device__ bf16  g_xs  [NTOK * DMODEL];
__device__ bf16  g_ab  [NTOK * DMODEL];         // attn big
__device__ bf16  g_as  [NTOK * DMODEL];         // attn small
__device__ float g_h1  [NTOK * F1];
__device__ float g_zero[DMODEL];                // stays zero

// ================= helpers =================
__device__ __forceinline__ uint32_t smem_u32(const void* p) {
    uint32_t a;
    asm("{ .reg .u64 t; cvta.to.shared.u64 t, %1; cvt.u32.u64 %0, t; }" : "=r"(a) : "l"(p));
    return a;
}
__device__ __forceinline__ void cp16(uint32_t dst, const void* src) {
    asm volatile("cp.async.cg.shared.global [%0], [%1], 16;" :: "r"(dst), "l"(src));
}
#define CP_COMMIT() asm volatile("cp.async.commit_group;" ::: "memory")
#define CP_WAIT1()  asm volatile("cp.async.wait_group 1;" ::: "memory")
#define CP_WAIT0()  asm volatile("cp.async.wait_group 0;" ::: "memory")

__device__ __forceinline__ void mma_bf16(float& d0, float& d1, float& d2, float& d3,
                                         uint32_t a0, uint32_t a1, uint32_t a2, uint32_t a3,
                                         uint32_t b0, uint32_t b1) {
    asm volatile(
        "mma.sync.aligned.m16n8k16.row.col.f32.bf16.bf16.f32 "
        "{%0,%1,%2,%3}, {%4,%5,%6,%7}, {%8,%9}, {%0,%1,%2,%3};"
        : "+f"(d0), "+f"(d1), "+f"(d2), "+f"(d3)
        : "r"(a0), "r"(a1), "r"(a2), "r"(a3), "r"(b0), "r"(b1));
}
__device__ __forceinline__ uint32_t pack_bf16(float lo, float hi) {
    uint16_t l = __bfloat16_as_ushort(__float2bfloat16_rn(lo));
    uint16_t h = __bfloat16_as_ushort(__float2bfloat16_rn(hi));
    return (uint32_t)l | ((uint32_t)h << 16);
}

// ================= generic transpose =================
__global__ void transpose_kernel(const float* __restrict__ src, float* __restrict__ dst,
                                 int rows, int cols, int sstride) {
    __shared__ float tile[32][33];
    int c0 = blockIdx.x * 32, r0 = blockIdx.y * 32;
    int tx = threadIdx.x, ty = threadIdx.y;
#pragma unroll
    for (int i = 0; i < 32; i += 8)
        tile[ty + i][tx] = src[(long)(r0 + ty + i) * sstride + c0 + tx];
    __syncthreads();
#pragma unroll
    for (int i = 0; i < 32; i += 8)
        dst[(long)(c0 + ty + i) * rows + r0 + tx] = tile[tx][ty + i];
}

// ================= fp32 -> bf16 split of x =================
__global__ void split_x(const float4* __restrict__ x, uint2* __restrict__ xb,
                        uint2* __restrict__ xs) {
    long i = (long)blockIdx.x * 256 + threadIdx.x;
    float4 v = x[i];
    float bx = __bfloat162float(__float2bfloat16_rn(v.x));
    float by = __bfloat162float(__float2bfloat16_rn(v.y));
    float bz = __bfloat162float(__float2bfloat16_rn(v.z));
    float bw = __bfloat162float(__float2bfloat16_rn(v.w));
    uint2 b, s;
    b.x = pack_bf16(bx, by); b.y = pack_bf16(bz, bw);
    s.x = pack_bf16(v.x - bx, v.y - by);
    s.y = pack_bf16(v.z - bz, v.w - bw);
    xb[i] = b; xs[i] = s;
}

// ================= SIMT SGEMM (kv projection + W2gT) =================
__global__ __launch_bounds__(256, 2)
void sgemm_k1024(const float* __restrict__ A, const float* __restrict__ B,
                 const float* __restrict__ bias, float* __restrict__ C,
                 int Arows, int Ncols) {
    const int K = 1024;
    __shared__ float Asm[2][8][128];
    __shared__ float Bsm[2][8][128];
    int t = threadIdx.x;
    int rowBase = blockIdx.y * 128, colBase = blockIdx.x * 128;
    int a_r = t >> 1, a_k = (t & 1) * 4;
    int b_k = t >> 5, b_n = (t & 31) * 4;
    int m0 = (t >> 4) * 8, n0 = (t & 15) * 8;
    float acc[8][8];
#pragma unroll
    for (int i = 0; i < 8; i++)
#pragma unroll
        for (int j = 0; j < 8; j++) acc[i][j] = 0.f;
    const bool a_in = (rowBase + a_r) < Arows;
    const float* Aptr = A + (long)(rowBase + a_r) * K + a_k;
    const float* Bptr = B + (long)b_k * Ncols + colBase + b_n;
    float4 a_reg = make_float4(0, 0, 0, 0), b_reg;
    if (a_in) a_reg = *(const float4*)(Aptr);
    b_reg = *(const float4*)(Bptr);
    Asm[0][a_k + 0][a_r] = a_reg.x; Asm[0][a_k + 1][a_r] = a_reg.y;
    Asm[0][a_k + 2][a_r] = a_reg.z; Asm[0][a_k + 3][a_r] = a_reg.w;
    *(float4*)&Bsm[0][b_k][b_n] = b_reg;
    __syncthreads();
    const int KT = K / 8;
    for (int kt = 0; kt < KT; kt++) {
        int buf = kt & 1;
        if (kt + 1 < KT) {
            a_reg = make_float4(0, 0, 0, 0);
            if (a_in) a_reg = *(const float4*)(Aptr + (kt + 1) * 8);
            b_reg = *(const float4*)(Bptr + (long)(kt + 1) * 8 * Ncols);
        }
#pragma unroll
        for (int k = 0; k < 8; k++) {
            float a[8], b[8];
            *(float4*)&a[0] = *(float4*)&Asm[buf][k][m0];
            *(float4*)&a[4] = *(float4*)&Asm[buf][k][m0 + 4];
            *(float4*)&b[0] = *(float4*)&Bsm[buf][k][n0];
            *(float4*)&b[4] = *(float4*)&Bsm[buf][k][n0 + 4];
#pragma unroll
            for (int i = 0; i < 8; i++)
#pragma unroll
                for (int j = 0; j < 8; j++) acc[i][j] = fmaf(a[i], b[j], acc[i][j]);
        }
        if (kt + 1 < KT) {
            int nb = buf ^ 1;
            Asm[nb][a_k + 0][a_r] = a_reg.x; Asm[nb][a_k + 1][a_r] = a_reg.y;
            Asm[nb][a_k + 2][a_r] = a_reg.z; Asm[nb][a_k + 3][a_r] = a_reg.w;
            *(float4*)&Bsm[nb][b_k][b_n] = b_reg;
        }
        __syncthreads();
    }
#pragma unroll
    for (int i = 0; i < 8; i++) {
        int r = rowBase + m0 + i;
        if (r < Arows) {
            float o[8];
#pragma unroll
            for (int j = 0; j < 8; j++) o[j] = acc[i][j] + bias[colBase + n0 + j];
            *(float4*)&C[(long)r * Ncols + colBase + n0]     = *(float4*)&o[0];
            *(float4*)&C[(long)r * Ncols + colBase + n0 + 4] = *(float4*)&o[4];
        }
    }
}

// ================= build M^T (bf16 split) + c, reading wq directly =================
// block = one he (0..1023). MTb[he][d] = sum_hd wq[h*64+hd, d] * k[e][h*64+hd]
__global__ void build_M_c(const float* __restrict__ ipw, const float* __restrict__ ipb,
                          const float* __restrict__ kv,
                          bf16* __restrict__ MTb, bf16* __restrict__ MTs,
                          float* __restrict__ c) {
    int he = blockIdx.x;
    int h = he >> 6, e = he & 63;
    __shared__ float ke[64];
    int t = threadIdx.x;
    if (t < 64) ke[t] = kv[(long)e * 2048 + h * 64 + t];
    __syncthreads();
    const float* wq = ipw + (long)(h * 64) * 1024;
    for (int d = t; d < 1024; d += 256) {
        float s = 0.f;
#pragma unroll 8
        for (int hd = 0; hd < 64; hd++)
            s = fmaf(wq[(long)hd * 1024 + d], ke[hd], s);
        bf16 b = __float2bfloat16_rn(s);
        MTb[(long)he * 1024 + d] = b;
        MTs[(long)he * 1024 + d] = __float2bfloat16_rn(s - __bfloat162float(b));
    }
    if (t < 32) {
        float s = ke[t] * ipb[h * 64 + t] + ke[t + 32] * ipb[h * 64 + t + 32];
#pragma unroll
        for (int off = 16; off > 0; off >>= 1)
            s += __shfl_xor_sync(0xffffffffu, s, off);
        if (t == 0) c[he] = s;
    }
}

// ================= build Gt (bf16 split) + c2 =================
// block = one j (0..255). Gt[j][he] = sum_hd v[e][h*64+hd] * W2gT[j][h*64+hd]
// c2[j] = sum_d opb[d]*gw1[j][d] + gb1[j]
__global__ void build_Gt(const float* __restrict__ W2gT, const float* __restrict__ kv,
                         const float* __restrict__ gw1, const float* __restrict__ opb,
                         const float* __restrict__ gb1,
                         bf16* __restrict__ Gtb, bf16* __restrict__ Gts,
                         float* __restrict__ c2) {
    int j = blockIdx.x;
    __shared__ float wrow[1024];
    int t = threadIdx.x;
    for (int i = t; i < 1024; i += 256) wrow[i] = W2gT[(long)j * 1024 + i];
    __syncthreads();
    for (int he = t; he < 1024; he += 256) {
        int h = he >> 6, e = he & 63;
        const float* v = kv + (long)e * 2048 + 1024 + h * 64;
        float s = 0.f;
#pragma unroll 8
        for (int hd = 0; hd < 64; hd++)
            s = fmaf(v[hd], wrow[h * 64 + hd], s);
        bf16 b = __float2bfloat16_rn(s);
        Gtb[(long)j * 1024 + he] = b;
        Gts[(long)j * 1024 + he] = __float2bfloat16_rn(s - __bfloat162float(b));
    }
    if (t < 32) {
        float s = 0.f;
        const float* g = gw1 + (long)j * 1024;
        for (int d = t; d < 1024; d += 32) s = fmaf(opb[d], g[d], s);
#pragma unroll
        for (int off = 16; off > 0; off >>= 1)
            s += __shfl_xor_sync(0xffffffffu, s, off);
        if (t == 0) c2[j] = s + gb1[j];
    }
}

// ================= bf16 3-split tensor-core GEMM (mma.sync) =================
// D[16384 x N] = (Ab+As)[16384 x 1024] * (Bb+Bs)[N x 1024]^T + bias  (drop As*Bs)
// MODE 1: *0.125, softmax over 64-col groups, bf16-split store to (outB, outS)
// MODE 2: exact GELU, fp32 store to outF
#define ROWW 20
#define TILE_W (128 * ROWW)
#define STAGE_W (4 * TILE_W)
#define SMEM_BYTES (2 * STAGE_W * 4)   // 81920

template<int MODE>
__global__ __launch_bounds__(256)
void tgemm(const bf16* __restrict__ Ab, const bf16* __restrict__ As,
           const bf16* __restrict__ Bb, const bf16* __restrict__ Bs,
           const float* __restrict__ bias,
           uint32_t* __restrict__ outB, uint32_t* __restrict__ outS,
           float* __restrict__ outF, int Ncols) {
    extern __shared__ uint32_t sm32[];
    uint32_t smu = smem_u32(sm32);

    const int t = threadIdx.x;
    const int w = t >> 5, lane = t & 31;
    const int wm = w >> 1, wn = w & 1;
    const int q = lane >> 2, c4 = lane & 3;

    const int rowBase = blockIdx.y * 128;
    const int colBase = blockIdx.x * 128;

    const int lr = t >> 1;
    const int ls = t & 1;
    const bf16* gAb = Ab + (long)(rowBase + lr) * 1024;
    const bf16* gAs = As + (long)(rowBase + lr) * 1024;
    const bf16* gBb = Bb + (long)(colBase + lr) * 1024;
    const bf16* gBs = Bs + (long)(colBase + lr) * 1024;
    const uint32_t dRow = smu + lr * (ROWW * 4);

    float acc[2][8][4];
#pragma unroll
    for (int mt = 0; mt < 2; mt++)
#pragma unroll
        for (int nt = 0; nt < 8; nt++)
#pragma unroll
            for (int i = 0; i < 4; i++) acc[mt][nt][i] = 0.f;

#define LOAD_STAGE(st, ck) do {                                                  \
    int kofs = (ck) * 32;                                                        \
    uint32_t sb = (st) * (STAGE_W * 4);                                          \
    _Pragma("unroll")                                                            \
    for (int j = 0; j < 2; j++) {                                                \
        int seg = ls * 2 + j;                                                    \
        cp16(dRow + sb + 0 * TILE_W * 4 + seg * 16, gAb + kofs + seg * 8);       \
        cp16(dRow + sb + 1 * TILE_W * 4 + seg * 16, gAs + kofs + seg * 8);       \
        cp16(dRow + sb + 2 * TILE_W * 4 + seg * 16, gBb + kofs + seg * 8);       \
        cp16(dRow + sb + 3 * TILE_W * 4 + seg * 16, gBs + kofs + seg * 8);       \
    }                                                                            \
} while (0)

    LOAD_STAGE(0, 0);
    CP_COMMIT();

    const int NC = 1024 / 32;
    for (int ck = 0; ck < NC; ck++) {
        int buf = ck & 1;
        if (ck + 1 < NC) {
            LOAD_STAGE(buf ^ 1, ck + 1);
            CP_COMMIT();
            CP_WAIT1();
        } else {
            CP_WAIT0();
        }
        __syncthreads();

        const uint32_t* sAb = sm32 + buf * STAGE_W;
        const uint32_t* sAs = sAb + TILE_W;
        const uint32_t* sBb = sAb + 2 * TILE_W;
        const uint32_t* sBs = sAb + 3 * TILE_W;

#pragma unroll
        for (int ks = 0; ks < 2; ks++) {
            uint32_t fab[2][4], fas[2][4], fbb[8][2], fbs[8][2];
#pragma unroll
            for (int mt = 0; mt < 2; mt++) {
                int base = (wm * 32 + mt * 16 + q) * ROWW + 8 * ks + c4;
                fab[mt][0] = sAb[base];           fab[mt][1] = sAb[base + 8 * ROWW];
                fab[mt][2] = sAb[base + 4];       fab[mt][3] = sAb[base + 8 * ROWW + 4];
                fas[mt][0] = sAs[base];           fas[mt][1] = sAs[base + 8 * ROWW];
                fas[mt][2] = sAs[base + 4];       fas[mt][3] = sAs[base + 8 * ROWW + 4];
            }
#pragma unroll
            for (int nt = 0; nt < 8; nt++) {
                int bb = (wn * 64 + nt * 8 + q) * ROWW + 8 * ks + c4;
                fbb[nt][0] = sBb[bb]; fbb[nt][1] = sBb[bb + 4];
                fbs[nt][0] = sBs[bb]; fbs[nt][1] = sBs[bb + 4];
            }
#pragma unroll
            for (int nt = 0; nt < 8; nt++)
#pragma unroll
                for (int mt = 0; mt < 2; mt++)
                    mma_bf16(acc[mt][nt][0], acc[mt][nt][1], acc[mt][nt][2], acc[mt][nt][3],
                             fab[mt][0], fab[mt][1], fab[mt][2], fab[mt][3],
                             fbb[nt][0], fbb[nt][1]);
#pragma unroll
            for (int nt = 0; nt < 8; nt++)
#pragma unroll
                for (int mt = 0; mt < 2; mt++)
                    mma_bf16(acc[mt][nt][0], acc[mt][nt][1], acc[mt][nt][2], acc[mt][nt][3],
                             fab[mt][0], fab[mt][1], fab[mt][2], fab[mt][3],
                             fbs[nt][0], fbs[nt][1]);
#pragma unroll
            for (int nt = 0; nt < 8; nt++)
#pragma unroll
                for (int mt = 0; mt < 2; mt++)
                    mma_bf16(acc[mt][nt][0], acc[mt][nt][1], acc[mt][nt][2], acc[mt][nt][3],
                             fas[mt][0], fas[mt][1], fas[mt][2], fas[mt][3],
                             fbb[nt][0], fbb[nt][1]);
        }
        __syncthreads();
    }

    // ================= epilogue =================
    const int colB = colBase + wn * 64;
    float bv[16];
#pragma unroll
    for (int nt = 0; nt < 8; nt++) {
#pragma unroll
        for (int j = 0; j < 2; j++)
            bv[nt * 2 + j] = bias[colB + nt * 8 + 2 * c4 + j];
    }

#pragma unroll
    for (int mt = 0; mt < 2; mt++) {
#pragma unroll
        for (int h = 0; h < 2; h++) {
            int row = rowBase + wm * 32 + mt * 16 + q + h * 8;
            float v[16];
#pragma unroll
            for (int nt = 0; nt < 8; nt++) {
                v[nt * 2 + 0] = acc[mt][nt][2 * h + 0] + bv[nt * 2 + 0];
                v[nt * 2 + 1] = acc[mt][nt][2 * h + 1] + bv[nt * 2 + 1];
            }
            if (MODE == 1) {
#pragma unroll
                for (int i = 0; i < 16; i++) v[i] *= 0.125f;
                float m = v[0];
#pragma unroll
                for (int i = 1; i < 16; i++) m = fmaxf(m, v[i]);
                m = fmaxf(m, __shfl_xor_sync(0xffffffffu, m, 1));
                m = fmaxf(m, __shfl_xor_sync(0xffffffffu, m, 2));
                float s = 0.f;
#pragma unroll
                for (int i = 0; i < 16; i++) { v[i] = expf(v[i] - m); s += v[i]; }
                s += __shfl_xor_sync(0xffffffffu, s, 1);
                s += __shfl_xor_sync(0xffffffffu, s, 2);
                float inv = 1.f / s;
#pragma unroll
                for (int i = 0; i < 16; i++) v[i] *= inv;
                uint32_t* ob = outB + (long)row * (Ncols / 2) + (colB >> 1) + c4;
                uint32_t* os = outS + (long)row * (Ncols / 2) + (colB >> 1) + c4;
#pragma unroll
                for (int nt = 0; nt < 8; nt++) {
                    float v0 = v[nt * 2], v1 = v[nt * 2 + 1];
                    float b0 = __bfloat162float(__float2bfloat16_rn(v0));
                    float b1 = __bfloat162float(__float2bfloat16_rn(v1));
                    ob[nt * 4] = pack_bf16(b0, b1);
                    os[nt * 4] = pack_bf16(v0 - b0, v1 - b1);
                }
            }
            if (MODE == 2) {
#pragma unroll
                for (int i = 0; i < 16; i++)
                    v[i] = 0.5f * v[i] * (1.0f + erff(v[i] * 0.70710678118654752f));
                float* op = outF + (long)row * Ncols + colB + 2 * c4;
#pragma unroll
                for (int nt = 0; nt < 8; nt++) {
                    op[nt * 8 + 0] = v[nt * 2 + 0];
                    op[nt * 8 + 1] = v[nt * 2 + 1];
                }
            }
        }
    }
#undef LOAD_STAGE
}

// ================= gating: logits + softmax + top-2 =================
__global__ void gating_kernel(const float* __restrict__ h1, const float* __restrict__ w2,
                              const float* __restrict__ b2, float* __restrict__ out) {
    __shared__ float hrow[4][F1];
    __shared__ float lg[4][NEXP];
    int t = threadIdx.x;
    int grp = t >> 6, e = t & 63;
    int token = blockIdx.x * 4 + grp;
    for (int j = e; j < F1; j += 64) hrow[grp][j] = h1[(long)token * F1 + j];
    __syncthreads();
    float acc = 0.f;
#pragma unroll 8
    for (int j = 0; j < F1; j++) acc = fmaf(hrow[grp][j], w2[e * F1 + j], acc);
    lg[grp][e] = acc + b2[e];
    __syncthreads();
    if (e == 0) {
        const float* L = lg[grp];
        int i1 = 0; float v1 = L[0];
        for (int k = 1; k < NEXP; k++) if (L[k] > v1) { v1 = L[k]; i1 = k; }
        int i2 = -1; float v2 = -1e30f;
        for (int k = 0; k < NEXP; k++) if (k != i1 && L[k] > v2) { v2 = L[k]; i2 = k; }
        float s = 0.f;
        for (int k = 0; k < NEXP; k++) s += expf(L[k] - v1);
        float p1 = 1.0f / s;
        float p2 = expf(v2 - v1) / s;
        float wsum = p1 + p2 + 1e-8f;
        out[token * 2 + 0] = (float)i1;
        out[token * 2 + 1] = (float)i2;
        out[NTOK * 2 + token * 2 + 0] = p1 / wsum;
        out[NTOK * 2 + token * 2 + 1] = p2 / wsum;
    }
}

// ================= launch =================
extern "C" void kernel_launch(void* const* d_in, const int* in_sizes, int n_in,
                              void* d_out, int out_size) {
    const float* x   = (const float*)d_in[0];
    const float* emb = (const float*)d_in[1];
    const float* ipw = (const float*)d_in[2];
    const float* ipb = (const float*)d_in[3];
    const float* opw = (const float*)d_in[4];
    const float* opb = (const float*)d_in[5];
    const float* gw1 = (const float*)d_in[6];
    const float* gb1 = (const float*)d_in[7];
    const float* gw2 = (const float*)d_in[8];
    const float* gb2 = (const float*)d_in[9];
    float* out = (float*)d_out;

    float *wkvT, *kv, *c, *W2gT, *c2, *h1, *zero;
    bf16 *MTb, *MTs, *Gtb, *Gts, *xb, *xs, *ab, *as_;
    cudaGetSymbolAddress((void**)&wkvT, g_wkvT);
    cudaGetSymbolAddress((void**)&kv,   g_kv);
    cudaGetSymbolAddress((void**)&c,    g_c);
    cudaGetSymbolAddress((void**)&W2gT, g_W2gT);
    cudaGetSymbolAddress((void**)&c2,   g_c2);
    cudaGetSymbolAddress((void**)&h1,   g_h1);
    cudaGetSymbolAddress((void**)&zero, g_zero);
    cudaGetSymbolAddress((void**)&MTb,  g_MTb);
    cudaGetSymbolAddress((void**)&MTs,  g_MTs);
    cudaGetSymbolAddress((void**)&Gtb,  g_Gtb);
    cudaGetSymbolAddress((void**)&Gts,  g_Gts);
    cudaGetSymbolAddress((void**)&xb,   g_xb);
    cudaGetSymbolAddress((void**)&xs,   g_xs);
    cudaGetSymbolAddress((void**)&ab,   g_ab);
    cudaGetSymbolAddress((void**)&as_,  g_as);

    cudaFuncSetAttribute(tgemm<1>, cudaFuncAttributeMaxDynamicSharedMemorySize, SMEM_BYTES);
    cudaFuncSetAttribute(tgemm<2>, cudaFuncAttributeMaxDynamicSharedMemorySize, SMEM_BYTES);

    dim3 tb(32, 8);
    // L0: wkv^T (needed by kv projection)
    transpose_kernel<<<dim3(32, 64), tb>>>(ipw + 1024 * 1024, wkvT, 2048, 1024, 1024);
    // L1: split x into bf16 big/small
    split_x<<<NTOK * DMODEL / 4 / 256, 256>>>((const float4*)x, (uint2*)xb, (uint2*)xs);
    // L2: kv = emb @ wkv^T + b_kv   (64 x 2048)
    sgemm_k1024<<<dim3(16, 1), 256>>>(emb, wkvT, ipb + 1024, kv, 64, 2048);
    // L3: W2gT = gw1 @ wo          (256 x 1024)
    sgemm_k1024<<<dim3(8, 2), 256>>>(gw1, opw, zero, W2gT, 256, 1024);
    // L4: M^T (split) + c
    build_M_c<<<1024, 256>>>(ipw, ipb, kv, MTb, MTs, c);
    // L5: Gt (split) + c2
    build_Gt<<<256, 256>>>(W2gT, kv, gw1, opb, gb1, Gtb, Gts, c2);
    // L6: GEMM1 softmax((x@M + c)/8) -> attn (bf16 split)
    tgemm<1><<<dim3(8, 128), 256, SMEM_BYTES>>>(xb, xs, MTb, MTs, c,
                                                (uint32_t*)ab, (uint32_t*)as_, nullptr, 1024);
    // L7: GEMM2' h1 = gelu(attn@Gt^T + c2)   (16384 x 256)
    tgemm<2><<<dim3(2, 128), 256, SMEM_BYTES>>>(ab, as_, Gtb, Gts, c2,
                                                nullptr, nullptr, h1, 256);
    // L8: gating
    gating_kernel<<<NTOK / 4, 256>>>(h1, gw2, gb2, out);
    (void)in_sizes; (void)n_in; (void)out_size;
}

// round 6
// speedup vs baseline: 2.0609x; 1.1886x over previous
#include <cuda_runtime.h>
#include <cuda_bf16.h>
#include <math.h>
#include <stdint.h>

#define NTOK   16384
#define DMODEL 1024
#define NEXP   64
#define F1     256

typedef __nv_bfloat16 bf16;

// ================= device scratch =================
__device__ float g_wkvT[DMODEL * 2 * DMODEL];   // [k][n]
__device__ float g_kv  [NEXP * 2 * DMODEL];     // [e][0:1024]=k, [1024:2048]=v
__device__ float g_c   [DMODEL];                // score bias per (h,e)
__device__ float g_W2gT[F1 * DMODEL];           // [j][i] = sum_d gw1[j,d]*wo[d,i]
__device__ float g_c2  [F1];                    // opb@gw1^T + gb1
__device__ float g_part[8 * F1 * DMODEL];       // split-K partials (8 MB)
__device__ bf16  g_MTb [DMODEL * DMODEL];       // [he][d]
__device__ bf16  g_MTs [DMODEL * DMODEL];
__device__ bf16  g_Gtb [F1 * DMODEL];           // [j][he]
__device__ bf16  g_Gts [F1 * DMODEL];
__device__ bf16  g_xb  [NTOK * DMODEL];
__device__ bf16  g_xs  [NTOK * DMODEL];
__device__ bf16  g_ab  [NTOK * DMODEL];         // attn big
__device__ bf16  g_as  [NTOK * DMODEL];         // attn small
__device__ float g_h1  [NTOK * F1];
__device__ float g_zero[DMODEL];                // stays zero

// ================= helpers =================
__device__ __forceinline__ uint32_t smem_u32(const void* p) {
    uint32_t a;
    asm("{ .reg .u64 t; cvta.to.shared.u64 t, %1; cvt.u32.u64 %0, t; }" : "=r"(a) : "l"(p));
    return a;
}
__device__ __forceinline__ void cp16(uint32_t dst, const void* src) {
    asm volatile("cp.async.cg.shared.global [%0], [%1], 16;" :: "r"(dst), "l"(src));
}
#define CP_COMMIT() asm volatile("cp.async.commit_group;" ::: "memory")
#define CP_WAIT1()  asm volatile("cp.async.wait_group 1;" ::: "memory")
#define CP_WAIT0()  asm volatile("cp.async.wait_group 0;" ::: "memory")

__device__ __forceinline__ void mma_bf16(float& d0, float& d1, float& d2, float& d3,
                                         uint32_t a0, uint32_t a1, uint32_t a2, uint32_t a3,
                                         uint32_t b0, uint32_t b1) {
    asm volatile(
        "mma.sync.aligned.m16n8k16.row.col.f32.bf16.bf16.f32 "
        "{%0,%1,%2,%3}, {%4,%5,%6,%7}, {%8,%9}, {%0,%1,%2,%3};"
        : "+f"(d0), "+f"(d1), "+f"(d2), "+f"(d3)
        : "r"(a0), "r"(a1), "r"(a2), "r"(a3), "r"(b0), "r"(b1));
}
__device__ __forceinline__ uint32_t pack_bf16(float lo, float hi) {
    uint16_t l = __bfloat16_as_ushort(__float2bfloat16_rn(lo));
    uint16_t h = __bfloat16_as_ushort(__float2bfloat16_rn(hi));
    return (uint32_t)l | ((uint32_t)h << 16);
}

// ================= generic transpose =================
__global__ void transpose_kernel(const float* __restrict__ src, float* __restrict__ dst,
                                 int rows, int cols, int sstride) {
    __shared__ float tile[32][33];
    int c0 = blockIdx.x * 32, r0 = blockIdx.y * 32;
    int tx = threadIdx.x, ty = threadIdx.y;
#pragma unroll
    for (int i = 0; i < 32; i += 8)
        tile[ty + i][tx] = src[(long)(r0 + ty + i) * sstride + c0 + tx];
    __syncthreads();
#pragma unroll
    for (int i = 0; i < 32; i += 8)
        dst[(long)(c0 + ty + i) * rows + r0 + tx] = tile[tx][ty + i];
}

// ================= fp32 -> bf16 split of x =================
__global__ void split_x(const float4* __restrict__ x, uint2* __restrict__ xb,
                        uint2* __restrict__ xs) {
    long i = (long)blockIdx.x * 256 + threadIdx.x;
    float4 v = x[i];
    float bx = __bfloat162float(__float2bfloat16_rn(v.x));
    float by = __bfloat162float(__float2bfloat16_rn(v.y));
    float bz = __bfloat162float(__float2bfloat16_rn(v.z));
    float bw = __bfloat162float(__float2bfloat16_rn(v.w));
    uint2 b, s;
    b.x = pack_bf16(bx, by); b.y = pack_bf16(bz, bw);
    s.x = pack_bf16(v.x - bx, v.y - by);
    s.y = pack_bf16(v.z - bz, v.w - bw);
    xb[i] = b; xs[i] = s;
}

// ================= split-K SIMT SGEMM =================
// P[z][Arows x N] partial for K-slice z (128 wide, K total 1024).
// A [Arows x 1024] row-major, B [1024 x N] row-major.
// grid (N/128, Arows/64, 8), block 256. Tile 64 x 128.
__global__ __launch_bounds__(256)
void sgemm_splitk(const float* __restrict__ A, const float* __restrict__ B,
                  float* __restrict__ P, int Arows, int N) {
    __shared__ float As[8][68];
    __shared__ float Bs[8][128];
    const int t = threadIdx.x;
    const int rowBase = blockIdx.y * 64;
    const int colBase = blockIdx.x * 128;
    const int k0 = blockIdx.z * 128;
    const int m0 = (t >> 4) * 4;
    const int n0 = (t & 15) * 8;
    const int am = t >> 2, akq = (t & 3) * 2;
    const int bn = t & 127, bkb = t >> 7;

    float acc[4][8];
#pragma unroll
    for (int i = 0; i < 4; i++)
#pragma unroll
        for (int j = 0; j < 8; j++) acc[i][j] = 0.f;

    for (int kc = 0; kc < 16; kc++) {
        int kk = k0 + kc * 8;
        float2 av = *(const float2*)(A + (long)(rowBase + am) * 1024 + kk + akq);
        As[akq][am] = av.x; As[akq + 1][am] = av.y;
#pragma unroll
        for (int j = 0; j < 4; j++)
            Bs[bkb + 2 * j][bn] = B[(long)(kk + bkb + 2 * j) * N + colBase + bn];
        __syncthreads();
#pragma unroll
        for (int k = 0; k < 8; k++) {
            float a[4], b[8];
            *(float4*)&a[0] = *(const float4*)&As[k][m0];
            *(float4*)&b[0] = *(const float4*)&Bs[k][n0];
            *(float4*)&b[4] = *(const float4*)&Bs[k][n0 + 4];
#pragma unroll
            for (int i = 0; i < 4; i++)
#pragma unroll
                for (int j = 0; j < 8; j++)
                    acc[i][j] = fmaf(a[i], b[j], acc[i][j]);
        }
        __syncthreads();
    }

    float* Pz = P + (long)blockIdx.z * Arows * N;
#pragma unroll
    for (int i = 0; i < 4; i++) {
        float* op = Pz + (long)(rowBase + m0 + i) * N + colBase + n0;
        *(float4*)op       = make_float4(acc[i][0], acc[i][1], acc[i][2], acc[i][3]);
        *(float4*)(op + 4) = make_float4(acc[i][4], acc[i][5], acc[i][6], acc[i][7]);
    }
}

// ================= split-K reduce + bias =================
__global__ void reduce_splitk(const float* __restrict__ P, const float* __restrict__ bias,
                              float* __restrict__ C, int total, int N) {
    int i = blockIdx.x * 256 + threadIdx.x;
    if (i < total) {
        float s = 0.f;
#pragma unroll
        for (int z = 0; z < 8; z++) s += P[(long)z * total + i];
        C[i] = s + bias[i % N];
    }
}

// ================= build M^T (bf16 split) + c =================
__global__ void build_M_c(const float* __restrict__ ipw, const float* __restrict__ ipb,
                          const float* __restrict__ kv,
                          bf16* __restrict__ MTb, bf16* __restrict__ MTs,
                          float* __restrict__ c) {
    int he = blockIdx.x;
    int h = he >> 6, e = he & 63;
    __shared__ float ke[64];
    int t = threadIdx.x;
    if (t < 64) ke[t] = kv[(long)e * 2048 + h * 64 + t];
    __syncthreads();
    const float* wq = ipw + (long)(h * 64) * 1024;
    for (int d = t; d < 1024; d += 256) {
        float s = 0.f;
#pragma unroll 8
        for (int hd = 0; hd < 64; hd++)
            s = fmaf(wq[(long)hd * 1024 + d], ke[hd], s);
        bf16 b = __float2bfloat16_rn(s);
        MTb[(long)he * 1024 + d] = b;
        MTs[(long)he * 1024 + d] = __float2bfloat16_rn(s - __bfloat162float(b));
    }
    if (t < 32) {
        float s = ke[t] * ipb[h * 64 + t] + ke[t + 32] * ipb[h * 64 + t + 32];
#pragma unroll
        for (int off = 16; off > 0; off >>= 1)
            s += __shfl_xor_sync(0xffffffffu, s, off);
        if (t == 0) c[he] = s;
    }
}

// ================= build Gt (bf16 split) + c2 =================
__global__ void build_Gt(const float* __restrict__ W2gT, const float* __restrict__ kv,
                         const float* __restrict__ gw1, const float* __restrict__ opb,
                         const float* __restrict__ gb1,
                         bf16* __restrict__ Gtb, bf16* __restrict__ Gts,
                         float* __restrict__ c2) {
    int j = blockIdx.x;
    __shared__ float wrow[1024];
    int t = threadIdx.x;
    for (int i = t; i < 1024; i += 256) wrow[i] = W2gT[(long)j * 1024 + i];
    __syncthreads();
    for (int he = t; he < 1024; he += 256) {
        int h = he >> 6, e = he & 63;
        const float* v = kv + (long)e * 2048 + 1024 + h * 64;
        float s = 0.f;
#pragma unroll 8
        for (int hd = 0; hd < 64; hd++)
            s = fmaf(v[hd], wrow[h * 64 + hd], s);
        bf16 b = __float2bfloat16_rn(s);
        Gtb[(long)j * 1024 + he] = b;
        Gts[(long)j * 1024 + he] = __float2bfloat16_rn(s - __bfloat162float(b));
    }
    if (t < 32) {
        float s = 0.f;
        const float* g = gw1 + (long)j * 1024;
        for (int d = t; d < 1024; d += 32) s = fmaf(opb[d], g[d], s);
#pragma unroll
        for (int off = 16; off > 0; off >>= 1)
            s += __shfl_xor_sync(0xffffffffu, s, off);
        if (t == 0) c2[j] = s + gb1[j];
    }
}

// ================= bf16 3-split tensor-core GEMM (mma.sync) =================
#define ROWW 20
#define TILE_W (128 * ROWW)
#define STAGE_W (4 * TILE_W)
#define SMEM_BYTES (2 * STAGE_W * 4)   // 81920

template<int MODE>
__global__ __launch_bounds__(256)
void tgemm(const bf16* __restrict__ Ab, const bf16* __restrict__ As,
           const bf16* __restrict__ Bb, const bf16* __restrict__ Bs,
           const float* __restrict__ bias,
           uint32_t* __restrict__ outB, uint32_t* __restrict__ outS,
           float* __restrict__ outF, int Ncols) {
    extern __shared__ uint32_t sm32[];
    uint32_t smu = smem_u32(sm32);

    const int t = threadIdx.x;
    const int w = t >> 5, lane = t & 31;
    const int wm = w >> 1, wn = w & 1;
    const int q = lane >> 2, c4 = lane & 3;

    const int rowBase = blockIdx.y * 128;
    const int colBase = blockIdx.x * 128;

    const int lr = t >> 1;
    const int ls = t & 1;
    const bf16* gAb = Ab + (long)(rowBase + lr) * 1024;
    const bf16* gAs = As + (long)(rowBase + lr) * 1024;
    const bf16* gBb = Bb + (long)(colBase + lr) * 1024;
    const bf16* gBs = Bs + (long)(colBase + lr) * 1024;
    const uint32_t dRow = smu + lr * (ROWW * 4);

    float acc[2][8][4];
#pragma unroll
    for (int mt = 0; mt < 2; mt++)
#pragma unroll
        for (int nt = 0; nt < 8; nt++)
#pragma unroll
            for (int i = 0; i < 4; i++) acc[mt][nt][i] = 0.f;

#define LOAD_STAGE(st, ck) do {                                                  \
    int kofs = (ck) * 32;                                                        \
    uint32_t sb = (st) * (STAGE_W * 4);                                          \
    _Pragma("unroll")                                                            \
    for (int j = 0; j < 2; j++) {                                                \
        int seg = ls * 2 + j;                                                    \
        cp16(dRow + sb + 0 * TILE_W * 4 + seg * 16, gAb + kofs + seg * 8);       \
        cp16(dRow + sb + 1 * TILE_W * 4 + seg * 16, gAs + kofs + seg * 8);       \
        cp16(dRow + sb + 2 * TILE_W * 4 + seg * 16, gBb + kofs + seg * 8);       \
        cp16(dRow + sb + 3 * TILE_W * 4 + seg * 16, gBs + kofs + seg * 8);       \
    }                                                                            \
} while (0)

    LOAD_STAGE(0, 0);
    CP_COMMIT();

    const int NC = 1024 / 32;
    for (int ck = 0; ck < NC; ck++) {
        int buf = ck & 1;
        if (ck + 1 < NC) {
            LOAD_STAGE(buf ^ 1, ck + 1);
            CP_COMMIT();
            CP_WAIT1();
        } else {
            CP_WAIT0();
        }
        __syncthreads();

        const uint32_t* sAb = sm32 + buf * STAGE_W;
        const uint32_t* sAs = sAb + TILE_W;
        const uint32_t* sBb = sAb + 2 * TILE_W;
        const uint32_t* sBs = sAb + 3 * TILE_W;

#pragma unroll
        for (int ks = 0; ks < 2; ks++) {
            uint32_t fab[2][4], fas[2][4], fbb[8][2], fbs[8][2];
#pragma unroll
            for (int mt = 0; mt < 2; mt++) {
                int base = (wm * 32 + mt * 16 + q) * ROWW + 8 * ks + c4;
                fab[mt][0] = sAb[base];           fab[mt][1] = sAb[base + 8 * ROWW];
                fab[mt][2] = sAb[base + 4];       fab[mt][3] = sAb[base + 8 * ROWW + 4];
                fas[mt][0] = sAs[base];           fas[mt][1] = sAs[base + 8 * ROWW];
                fas[mt][2] = sAs[base + 4];       fas[mt][3] = sAs[base + 8 * ROWW + 4];
            }
#pragma unroll
            for (int nt = 0; nt < 8; nt++) {
                int bb = (wn * 64 + nt * 8 + q) * ROWW + 8 * ks + c4;
                fbb[nt][0] = sBb[bb]; fbb[nt][1] = sBb[bb + 4];
                fbs[nt][0] = sBs[bb]; fbs[nt][1] = sBs[bb + 4];
            }
#pragma unroll
            for (int nt = 0; nt < 8; nt++)
#pragma unroll
                for (int mt = 0; mt < 2; mt++)
                    mma_bf16(acc[mt][nt][0], acc[mt][nt][1], acc[mt][nt][2], acc[mt][nt][3],
                             fab[mt][0], fab[mt][1], fab[mt][2], fab[mt][3],
                             fbb[nt][0], fbb[nt][1]);
#pragma unroll
            for (int nt = 0; nt < 8; nt++)
#pragma unroll
                for (int mt = 0; mt < 2; mt++)
                    mma_bf16(acc[mt][nt][0], acc[mt][nt][1], acc[mt][nt][2], acc[mt][nt][3],
                             fab[mt][0], fab[mt][1], fab[mt][2], fab[mt][3],
                             fbs[nt][0], fbs[nt][1]);
#pragma unroll
            for (int nt = 0; nt < 8; nt++)
#pragma unroll
                for (int mt = 0; mt < 2; mt++)
                    mma_bf16(acc[mt][nt][0], acc[mt][nt][1], acc[mt][nt][2], acc[mt][nt][3],
                             fas[mt][0], fas[mt][1], fas[mt][2], fas[mt][3],
                             fbb[nt][0], fbb[nt][1]);
        }
        __syncthreads();
    }

    const int colB = colBase + wn * 64;
    float bv[16];
#pragma unroll
    for (int nt = 0; nt < 8; nt++) {
#pragma unroll
        for (int j = 0; j < 2; j++)
            bv[nt * 2 + j] = bias[colB + nt * 8 + 2 * c4 + j];
    }

#pragma unroll
    for (int mt = 0; mt < 2; mt++) {
#pragma unroll
        for (int h = 0; h < 2; h++) {
            int row = rowBase + wm * 32 + mt * 16 + q + h * 8;
            float v[16];
#pragma unroll
            for (int nt = 0; nt < 8; nt++) {
                v[nt * 2 + 0] = acc[mt][nt][2 * h + 0] + bv[nt * 2 + 0];
                v[nt * 2 + 1] = acc[mt][nt][2 * h + 1] + bv[nt * 2 + 1];
            }
            if (MODE == 1) {
#pragma unroll
                for (int i = 0; i < 16; i++) v[i] *= 0.125f;
                float m = v[0];
#pragma unroll
                for (int i = 1; i < 16; i++) m = fmaxf(m, v[i]);
                m = fmaxf(m, __shfl_xor_sync(0xffffffffu, m, 1));
                m = fmaxf(m, __shfl_xor_sync(0xffffffffu, m, 2));
                float s = 0.f;
#pragma unroll
                for (int i = 0; i < 16; i++) { v[i] = expf(v[i] - m); s += v[i]; }
                s += __shfl_xor_sync(0xffffffffu, s, 1);
                s += __shfl_xor_sync(0xffffffffu, s, 2);
                float inv = 1.f / s;
#pragma unroll
                for (int i = 0; i < 16; i++) v[i] *= inv;
                uint32_t* ob = outB + (long)row * (Ncols / 2) + (colB >> 1) + c4;
                uint32_t* os = outS + (long)row * (Ncols / 2) + (colB >> 1) + c4;
#pragma unroll
                for (int nt = 0; nt < 8; nt++) {
                    float v0 = v[nt * 2], v1 = v[nt * 2 + 1];
                    float b0 = __bfloat162float(__float2bfloat16_rn(v0));
                    float b1 = __bfloat162float(__float2bfloat16_rn(v1));
                    ob[nt * 4] = pack_bf16(b0, b1);
                    os[nt * 4] = pack_bf16(v0 - b0, v1 - b1);
                }
            }
            if (MODE == 2) {
#pragma unroll
                for (int i = 0; i < 16; i++)
                    v[i] = 0.5f * v[i] * (1.0f + erff(v[i] * 0.70710678118654752f));
                float* op = outF + (long)row * Ncols + colB + 2 * c4;
#pragma unroll
                for (int nt = 0; nt < 8; nt++) {
                    op[nt * 8 + 0] = v[nt * 2 + 0];
                    op[nt * 8 + 1] = v[nt * 2 + 1];
                }
            }
        }
    }
#undef LOAD_STAGE
}

// ================= gating: logits + softmax + top-2 =================
__global__ void gating_kernel(const float* __restrict__ h1, const float* __restrict__ w2,
                              const float* __restrict__ b2, float* __restrict__ out) {
    __shared__ float hrow[4][F1];
    __shared__ float lg[4][NEXP];
    int t = threadIdx.x;
    int grp = t >> 6, e = t & 63;
    int token = blockIdx.x * 4 + grp;
    for (int j = e; j < F1; j += 64) hrow[grp][j] = h1[(long)token * F1 + j];
    __syncthreads();
    float acc = 0.f;
#pragma unroll 8
    for (int j = 0; j < F1; j++) acc = fmaf(hrow[grp][j], w2[e * F1 + j], acc);
    lg[grp][e] = acc + b2[e];
    __syncthreads();
    if (e == 0) {
        const float* L = lg[grp];
        int i1 = 0; float v1 = L[0];
        for (int k = 1; k < NEXP; k++) if (L[k] > v1) { v1 = L[k]; i1 = k; }
        int i2 = -1; float v2 = -1e30f;
        for (int k = 0; k < NEXP; k++) if (k != i1 && L[k] > v2) { v2 = L[k]; i2 = k; }
        float s = 0.f;
        for (int k = 0; k < NEXP; k++) s += expf(L[k] - v1);
        float p1 = 1.0f / s;
        float p2 = expf(v2 - v1) / s;
        float wsum = p1 + p2 + 1e-8f;
        out[token * 2 + 0] = (float)i1;
        out[token * 2 + 1] = (float)i2;
        out[NTOK * 2 + token * 2 + 0] = p1 / wsum;
        out[NTOK * 2 + token * 2 + 1] = p2 / wsum;
    }
}

// ================= launch =================
extern "C" void kernel_launch(void* const* d_in, const int* in_sizes, int n_in,
                              void* d_out, int out_size) {
    const float* x   = (const float*)d_in[0];
    const float* emb = (const float*)d_in[1];
    const float* ipw = (const float*)d_in[2];
    const float* ipb = (const float*)d_in[3];
    const float* opw = (const float*)d_in[4];
    const float* opb = (const float*)d_in[5];
    const float* gw1 = (const float*)d_in[6];
    const float* gb1 = (const float*)d_in[7];
    const float* gw2 = (const float*)d_in[8];
    const float* gb2 = (const float*)d_in[9];
    float* out = (float*)d_out;

    float *wkvT, *kv, *c, *W2gT, *c2, *part, *h1, *zero;
    bf16 *MTb, *MTs, *Gtb, *Gts, *xb, *xs, *ab, *as_;
    cudaGetSymbolAddress((void**)&wkvT, g_wkvT);
    cudaGetSymbolAddress((void**)&kv,   g_kv);
    cudaGetSymbolAddress((void**)&c,    g_c);
    cudaGetSymbolAddress((void**)&W2gT, g_W2gT);
    cudaGetSymbolAddress((void**)&c2,   g_c2);
    cudaGetSymbolAddress((void**)&part, g_part);
    cudaGetSymbolAddress((void**)&h1,   g_h1);
    cudaGetSymbolAddress((void**)&zero, g_zero);
    cudaGetSymbolAddress((void**)&MTb,  g_MTb);
    cudaGetSymbolAddress((void**)&MTs,  g_MTs);
    cudaGetSymbolAddress((void**)&Gtb,  g_Gtb);
    cudaGetSymbolAddress((void**)&Gts,  g_Gts);
    cudaGetSymbolAddress((void**)&xb,   g_xb);
    cudaGetSymbolAddress((void**)&xs,   g_xs);
    cudaGetSymbolAddress((void**)&ab,   g_ab);
    cudaGetSymbolAddress((void**)&as_,  g_as);

    cudaFuncSetAttribute(tgemm<1>, cudaFuncAttributeMaxDynamicSharedMemorySize, SMEM_BYTES);
    cudaFuncSetAttribute(tgemm<2>, cudaFuncAttributeMaxDynamicSharedMemorySize, SMEM_BYTES);

    dim3 tb(32, 8);
    // L0: wkv^T
    transpose_kernel<<<dim3(32, 64), tb>>>(ipw + 1024 * 1024, wkvT, 2048, 1024, 1024);
    // L1: split x
    split_x<<<NTOK * DMODEL / 4 / 256, 256>>>((const float4*)x, (uint2*)xb, (uint2*)xs);
    // L2: kv partials (64 x 2048), split-K=8
    sgemm_splitk<<<dim3(16, 1, 8), 256>>>(emb, wkvT, part, 64, 2048);
    // L3: reduce kv (+ k/v bias)
    reduce_splitk<<<(64 * 2048 + 255) / 256, 256>>>(part, ipb + 1024, kv, 64 * 2048, 2048);
    // L4: M^T (split) + c
    build_M_c<<<1024, 256>>>(ipw, ipb, kv, MTb, MTs, c);
    // L5: GEMM1 softmax((x@M + c)/8) -> attn (bf16 split)   [profiled by ncu -s 5]
    tgemm<1><<<dim3(8, 128), 256, SMEM_BYTES>>>(xb, xs, MTb, MTs, c,
                                                (uint32_t*)ab, (uint32_t*)as_, nullptr, 1024);
    // L6: W2gT partials (256 x 1024), split-K=8
    sgemm_splitk<<<dim3(8, 4, 8), 256>>>(gw1, opw, part, 256, 1024);
    // L7: reduce W2gT (zero bias)
    reduce_splitk<<<(256 * 1024 + 255) / 256, 256>>>(part, zero, W2gT, 256 * 1024, 1024);
    // L8: Gt (split) + c2
    build_Gt<<<256, 256>>>(W2gT, kv, gw1, opb, gb1, Gtb, Gts, c2);
    // L9: GEMM2' h1 = gelu(attn@Gt^T + c2)   (16384 x 256)
    tgemm<2><<<dim3(2, 128), 256, SMEM_BYTES>>>(ab, as_, Gtb, Gts, c2,
                                                nullptr, nullptr, h1, 256);
    // L10: gating
    gating_kernel<<<NTOK / 4, 256>>>(h1, gw2, gb2, out);
    (void)in_sizes; (void)n_in; (void)out_size;
}

// round 8
// speedup vs baseline: 4.6238x; 2.2436x over previous
#include <cuda_runtime.h>
#include <cuda_bf16.h>
#include <math.h>
#include <stdint.h>

#define NTOK   16384
#define DMODEL 1024
#define NEXP   64
#define F1     256

typedef __nv_bfloat16 bf16;

// ================= device scratch =================
__device__ float g_wkvT[DMODEL * 2 * DMODEL];
__device__ float g_kv  [NEXP * 2 * DMODEL];
__device__ float g_c   [DMODEL];
__device__ float g_W2gT[F1 * DMODEL];
__device__ float g_c2  [F1];
__device__ float g_part[8 * F1 * DMODEL];
__device__ bf16  g_MTb [DMODEL * DMODEL];
__device__ bf16  g_MTs [DMODEL * DMODEL];
__device__ bf16  g_Gtb [F1 * DMODEL];
__device__ bf16  g_Gts [F1 * DMODEL];
__device__ bf16  g_xb  [NTOK * DMODEL];
__device__ bf16  g_xs  [NTOK * DMODEL];
__device__ bf16  g_ab  [NTOK * DMODEL];
__device__ bf16  g_as  [NTOK * DMODEL];
__device__ float g_h1  [NTOK * F1];
__device__ float g_zero[DMODEL];

// ================= helpers =================
__device__ __forceinline__ uint32_t smem_u32(const void* p) {
    uint32_t a;
    asm("{ .reg .u64 t; cvta.to.shared.u64 t, %1; cvt.u32.u64 %0, t; }" : "=r"(a) : "l"(p));
    return a;
}
__device__ __forceinline__ void cp16(uint32_t dst, const void* src) {
    asm volatile("cp.async.cg.shared.global [%0], [%1], 16;" :: "r"(dst), "l"(src));
}
#define CP_COMMIT() asm volatile("cp.async.commit_group;" ::: "memory")
#define CP_WAIT1()  asm volatile("cp.async.wait_group 1;" ::: "memory")
#define CP_WAIT0()  asm volatile("cp.async.wait_group 0;" ::: "memory")

#define LDSM4(r0, r1, r2, r3, a)                                               \
    asm volatile("ldmatrix.sync.aligned.m8n8.x4.shared.b16 {%0,%1,%2,%3}, [%4];" \
                 : "=r"(r0), "=r"(r1), "=r"(r2), "=r"(r3) : "r"(a))

__device__ __forceinline__ void mma_bf16(float& d0, float& d1, float& d2, float& d3,
                                         uint32_t a0, uint32_t a1, uint32_t a2, uint32_t a3,
                                         uint32_t b0, uint32_t b1) {
    asm volatile(
        "mma.sync.aligned.m16n8k16.row.col.f32.bf16.bf16.f32 "
        "{%0,%1,%2,%3}, {%4,%5,%6,%7}, {%8,%9}, {%0,%1,%2,%3};"
        : "+f"(d0), "+f"(d1), "+f"(d2), "+f"(d3)
        : "r"(a0), "r"(a1), "r"(a2), "r"(a3), "r"(b0), "r"(b1));
}
__device__ __forceinline__ uint32_t pack_bf16(float lo, float hi) {
    uint16_t l = __bfloat16_as_ushort(__float2bfloat16_rn(lo));
    uint16_t h = __bfloat16_as_ushort(__float2bfloat16_rn(hi));
    return (uint32_t)l | ((uint32_t)h << 16);
}

// ================= generic transpose =================
__global__ void transpose_kernel(const float* __restrict__ src, float* __restrict__ dst,
                                 int rows, int cols, int sstride) {
    __shared__ float tile[32][33];
    int c0 = blockIdx.x * 32, r0 = blockIdx.y * 32;
    int tx = threadIdx.x, ty = threadIdx.y;
#pragma unroll
    for (int i = 0; i < 32; i += 8)
        tile[ty + i][tx] = src[(long)(r0 + ty + i) * sstride + c0 + tx];
    __syncthreads();
#pragma unroll
    for (int i = 0; i < 32; i += 8)
        dst[(long)(c0 + ty + i) * rows + r0 + tx] = tile[tx][ty + i];
}

// ================= fp32 -> bf16 split of x =================
__global__ void split_x(const float4* __restrict__ x, uint2* __restrict__ xb,
                        uint2* __restrict__ xs) {
    long i = (long)blockIdx.x * 256 + threadIdx.x;
    float4 v = x[i];
    float bx = __bfloat162float(__float2bfloat16_rn(v.x));
    float by = __bfloat162float(__float2bfloat16_rn(v.y));
    float bz = __bfloat162float(__float2bfloat16_rn(v.z));
    float bw = __bfloat162float(__float2bfloat16_rn(v.w));
    uint2 b, s;
    b.x = pack_bf16(bx, by); b.y = pack_bf16(bz, bw);
    s.x = pack_bf16(v.x - bx, v.y - by);
    s.y = pack_bf16(v.z - bz, v.w - bw);
    xb[i] = b; xs[i] = s;
}

// ================= split-K SIMT SGEMM =================
__global__ __launch_bounds__(256)
void sgemm_splitk(const float* __restrict__ A, const float* __restrict__ B,
                  float* __restrict__ P, int Arows, int N) {
    __shared__ float As[8][68];
    __shared__ float Bs[8][128];
    const int t = threadIdx.x;
    const int rowBase = blockIdx.y * 64;
    const int colBase = blockIdx.x * 128;
    const int k0 = blockIdx.z * 128;
    const int m0 = (t >> 4) * 4;
    const int n0 = (t & 15) * 8;
    const int am = t >> 2, akq = (t & 3) * 2;
    const int bn = t & 127, bkb = t >> 7;

    float acc[4][8];
#pragma unroll
    for (int i = 0; i < 4; i++)
#pragma unroll
        for (int j = 0; j < 8; j++) acc[i][j] = 0.f;

    for (int kc = 0; kc < 16; kc++) {
        int kk = k0 + kc * 8;
        float2 av = *(const float2*)(A + (long)(rowBase + am) * 1024 + kk + akq);
        As[akq][am] = av.x; As[akq + 1][am] = av.y;
#pragma unroll
        for (int j = 0; j < 4; j++)
            Bs[bkb + 2 * j][bn] = B[(long)(kk + bkb + 2 * j) * N + colBase + bn];
        __syncthreads();
#pragma unroll
        for (int k = 0; k < 8; k++) {
            float a[4], b[8];
            *(float4*)&a[0] = *(const float4*)&As[k][m0];
            *(float4*)&b[0] = *(const float4*)&Bs[k][n0];
            *(float4*)&b[4] = *(const float4*)&Bs[k][n0 + 4];
#pragma unroll
            for (int i = 0; i < 4; i++)
#pragma unroll
                for (int j = 0; j < 8; j++)
                    acc[i][j] = fmaf(a[i], b[j], acc[i][j]);
        }
        __syncthreads();
    }

    float* Pz = P + (long)blockIdx.z * Arows * N;
#pragma unroll
    for (int i = 0; i < 4; i++) {
        float* op = Pz + (long)(rowBase + m0 + i) * N + colBase + n0;
        *(float4*)op       = make_float4(acc[i][0], acc[i][1], acc[i][2], acc[i][3]);
        *(float4*)(op + 4) = make_float4(acc[i][4], acc[i][5], acc[i][6], acc[i][7]);
    }
}

__global__ void reduce_splitk(const float* __restrict__ P, const float* __restrict__ bias,
                              float* __restrict__ C, int total, int N) {
    int i = blockIdx.x * 256 + threadIdx.x;
    if (i < total) {
        float s = 0.f;
#pragma unroll
        for (int z = 0; z < 8; z++) s += P[(long)z * total + i];
        C[i] = s + bias[i % N];
    }
}

// ================= build M^T (bf16 split) + c =================
__global__ void build_M_c(const float* __restrict__ ipw, const float* __restrict__ ipb,
                          const float* __restrict__ kv,
                          bf16* __restrict__ MTb, bf16* __restrict__ MTs,
                          float* __restrict__ c) {
    int he = blockIdx.x;
    int h = he >> 6, e = he & 63;
    __shared__ float ke[64];
    int t = threadIdx.x;
    if (t < 64) ke[t] = kv[(long)e * 2048 + h * 64 + t];
    __syncthreads();
    const float* wq = ipw + (long)(h * 64) * 1024;
    for (int d = t; d < 1024; d += 256) {
        float s = 0.f;
#pragma unroll 8
        for (int hd = 0; hd < 64; hd++)
            s = fmaf(wq[(long)hd * 1024 + d], ke[hd], s);
        bf16 b = __float2bfloat16_rn(s);
        MTb[(long)he * 1024 + d] = b;
        MTs[(long)he * 1024 + d] = __float2bfloat16_rn(s - __bfloat162float(b));
    }
    if (t < 32) {
        float s = ke[t] * ipb[h * 64 + t] + ke[t + 32] * ipb[h * 64 + t + 32];
#pragma unroll
        for (int off = 16; off > 0; off >>= 1)
            s += __shfl_xor_sync(0xffffffffu, s, off);
        if (t == 0) c[he] = s;
    }
}

// ================= build Gt (bf16 split) + c2 =================
__global__ void build_Gt(const float* __restrict__ W2gT, const float* __restrict__ kv,
                         const float* __restrict__ gw1, const float* __restrict__ opb,
                         const float* __restrict__ gb1,
                         bf16* __restrict__ Gtb, bf16* __restrict__ Gts,
                         float* __restrict__ c2) {
    int j = blockIdx.x;
    __shared__ float wrow[1024];
    int t = threadIdx.x;
    for (int i = t; i < 1024; i += 256) wrow[i] = W2gT[(long)j * 1024 + i];
    __syncthreads();
    for (int he = t; he < 1024; he += 256) {
        int h = he >> 6, e = he & 63;
        const float* v = kv + (long)e * 2048 + 1024 + h * 64;
        float s = 0.f;
#pragma unroll 8
        for (int hd = 0; hd < 64; hd++)
            s = fmaf(v[hd], wrow[h * 64 + hd], s);
        bf16 b = __float2bfloat16_rn(s);
        Gtb[(long)j * 1024 + he] = b;
        Gts[(long)j * 1024 + he] = __float2bfloat16_rn(s - __bfloat162float(b));
    }
    if (t < 32) {
        float s = 0.f;
        const float* g = gw1 + (long)j * 1024;
        for (int d = t; d < 1024; d += 32) s = fmaf(opb[d], g[d], s);
#pragma unroll
        for (int off = 16; off > 0; off >>= 1)
            s += __shfl_xor_sync(0xffffffffu, s, off);
        if (t == 0) c2[j] = s + gb1[j];
    }
}

// ================= bf16 3-split tensor-core GEMM (ldmatrix + mma.sync) =================
#define ROWW 20
#define TILE_B 10240                 // 128 rows * 80 B
#define STAGE_B (4 * TILE_B)         // 40960
#define SMEM_BYTES (2 * STAGE_B)     // 81920

template<int MODE>
__global__ __launch_bounds__(256, 2)
void tgemm(const bf16* __restrict__ Ab, const bf16* __restrict__ As,
           const bf16* __restrict__ Bb, const bf16* __restrict__ Bs,
           const float* __restrict__ bias,
           uint32_t* __restrict__ outB, uint32_t* __restrict__ outS,
           float* __restrict__ outF, int Ncols) {
    extern __shared__ uint32_t sm32[];
    uint32_t smu = smem_u32(sm32);

    const int t = threadIdx.x;
    const int w = t >> 5, lane = t & 31;
    const int wm = w >> 1, wn = w & 1;
    const int q = lane >> 2, c4 = lane & 3;

    const int rowBase = blockIdx.y * 128;
    const int colBase = blockIdx.x * 128;

    const int lr = t >> 1;
    const int ls = t & 1;
    const bf16* gAb = Ab + (long)(rowBase + lr) * 1024;
    const bf16* gAs = As + (long)(rowBase + lr) * 1024;
    const bf16* gBb = Bb + (long)(colBase + lr) * 1024;
    const bf16* gBs = Bs + (long)(colBase + lr) * 1024;
    const uint32_t dRow = smu + lr * (ROWW * 4);

    // per-lane ldmatrix byte offsets
    const int lm8 = lane & 7;
    const uint32_t aOff = (uint32_t)(wm * 32 + lm8 + ((lane >> 3) & 1) * 8) * 80
                          + ((lane >> 4) & 1) * 16;
    const uint32_t bOff = (uint32_t)(wn * 64 + lm8 + ((lane >> 4) & 1) * 8) * 80
                          + ((lane >> 3) & 1) * 16;

    float acc[2][8][4];
#pragma unroll
    for (int mt = 0; mt < 2; mt++)
#pragma unroll
        for (int nt = 0; nt < 8; nt++)
#pragma unroll
            for (int i = 0; i < 4; i++) acc[mt][nt][i] = 0.f;

#define LOAD_STAGE(st, ck) do {                                                  \
    int kofs = (ck) * 32;                                                        \
    uint32_t sb = (st) * STAGE_B;                                                \
    _Pragma("unroll")                                                            \
    for (int j = 0; j < 2; j++) {                                                \
        int seg = ls * 2 + j;                                                    \
        cp16(dRow + sb + 0 * TILE_B + seg * 16, gAb + kofs + seg * 8);           \
        cp16(dRow + sb + 1 * TILE_B + seg * 16, gAs + kofs + seg * 8);           \
        cp16(dRow + sb + 2 * TILE_B + seg * 16, gBb + kofs + seg * 8);           \
        cp16(dRow + sb + 3 * TILE_B + seg * 16, gBs + kofs + seg * 8);           \
    }                                                                            \
} while (0)

    LOAD_STAGE(0, 0);
    CP_COMMIT();

    const int NC = 1024 / 32;
    for (int ck = 0; ck < NC; ck++) {
        int buf = ck & 1;
        if (ck + 1 < NC) {
            LOAD_STAGE(buf ^ 1, ck + 1);
            CP_COMMIT();
            CP_WAIT1();
        } else {
            CP_WAIT0();
        }
        __syncthreads();

        const uint32_t s0 = smu + buf * STAGE_B;
        const uint32_t aAb = s0 + aOff;
        const uint32_t aAs = s0 + TILE_B + aOff;
        const uint32_t bBb = s0 + 2 * TILE_B + bOff;
        const uint32_t bBs = s0 + 3 * TILE_B + bOff;

#pragma unroll
        for (int ks = 0; ks < 2; ks++) {
            uint32_t fab[2][4], fas[2][4];
            LDSM4(fab[0][0], fab[0][1], fab[0][2], fab[0][3], aAb + ks * 32);
            LDSM4(fab[1][0], fab[1][1], fab[1][2], fab[1][3], aAb + 1280 + ks * 32);
            LDSM4(fas[0][0], fas[0][1], fas[0][2], fas[0][3], aAs + ks * 32);
            LDSM4(fas[1][0], fas[1][1], fas[1][2], fas[1][3], aAs + 1280 + ks * 32);
#pragma unroll
            for (int jh = 0; jh < 2; jh++) {
                uint32_t fbb[4][2], fbs[4][2];
                LDSM4(fbb[0][0], fbb[0][1], fbb[1][0], fbb[1][1],
                      bBb + (2 * jh) * 1280 + ks * 32);
                LDSM4(fbb[2][0], fbb[2][1], fbb[3][0], fbb[3][1],
                      bBb + (2 * jh + 1) * 1280 + ks * 32);
                LDSM4(fbs[0][0], fbs[0][1], fbs[1][0], fbs[1][1],
                      bBs + (2 * jh) * 1280 + ks * 32);
                LDSM4(fbs[2][0], fbs[2][1], fbs[3][0], fbs[3][1],
                      bBs + (2 * jh + 1) * 1280 + ks * 32);
#pragma unroll
                for (int l = 0; l < 4; l++)
#pragma unroll
                    for (int mt = 0; mt < 2; mt++) {
                        float* d = acc[mt][4 * jh + l];
                        mma_bf16(d[0], d[1], d[2], d[3],
                                 fab[mt][0], fab[mt][1], fab[mt][2], fab[mt][3],
                                 fbb[l][0], fbb[l][1]);
                    }
#pragma unroll
                for (int l = 0; l < 4; l++)
#pragma unroll
                    for (int mt = 0; mt < 2; mt++) {
                        float* d = acc[mt][4 * jh + l];
                        mma_bf16(d[0], d[1], d[2], d[3],
                                 fab[mt][0], fab[mt][1], fab[mt][2], fab[mt][3],
                                 fbs[l][0], fbs[l][1]);
                    }
#pragma unroll
                for (int l = 0; l < 4; l++)
#pragma unroll
                    for (int mt = 0; mt < 2; mt++) {
                        float* d = acc[mt][4 * jh + l];
                        mma_bf16(d[0], d[1], d[2], d[3],
                                 fas[mt][0], fas[mt][1], fas[mt][2], fas[mt][3],
                                 fbb[l][0], fbb[l][1]);
                    }
            }
        }
        __syncthreads();
    }

    // ================= epilogue =================
    const int colB = colBase + wn * 64;
    float bv[16];
#pragma unroll
    for (int nt = 0; nt < 8; nt++) {
#pragma unroll
        for (int j = 0; j < 2; j++)
            bv[nt * 2 + j] = bias[colB + nt * 8 + 2 * c4 + j];
    }

#pragma unroll
    for (int mt = 0; mt < 2; mt++) {
#pragma unroll
        for (int h = 0; h < 2; h++) {
            int row = rowBase + wm * 32 + mt * 16 + q + h * 8;
            float v[16];
#pragma unroll
            for (int nt = 0; nt < 8; nt++) {
                v[nt * 2 + 0] = acc[mt][nt][2 * h + 0] + bv[nt * 2 + 0];
                v[nt * 2 + 1] = acc[mt][nt][2 * h + 1] + bv[nt * 2 + 1];
            }
            if (MODE == 1) {
#pragma unroll
                for (int i = 0; i < 16; i++) v[i] *= 0.125f;
                float m = v[0];
#pragma unroll
                for (int i = 1; i < 16; i++) m = fmaxf(m, v[i]);
                m = fmaxf(m, __shfl_xor_sync(0xffffffffu, m, 1));
                m = fmaxf(m, __shfl_xor_sync(0xffffffffu, m, 2));
                float s = 0.f;
#pragma unroll
                for (int i = 0; i < 16; i++) { v[i] = expf(v[i] - m); s += v[i]; }
                s += __shfl_xor_sync(0xffffffffu, s, 1);
                s += __shfl_xor_sync(0xffffffffu, s, 2);
                float inv = 1.f / s;
#pragma unroll
                for (int i = 0; i < 16; i++) v[i] *= inv;
                uint32_t* ob = outB + (long)row * (Ncols / 2) + (colB >> 1) + c4;
                uint32_t* os = outS + (long)row * (Ncols / 2) + (colB >> 1) + c4;
#pragma unroll
                for (int nt = 0; nt < 8; nt++) {
                    float v0 = v[nt * 2], v1 = v[nt * 2 + 1];
                    float b0 = __bfloat162float(__float2bfloat16_rn(v0));
                    float b1 = __bfloat162float(__float2bfloat16_rn(v1));
                    ob[nt * 4] = pack_bf16(b0, b1);
                    os[nt * 4] = pack_bf16(v0 - b0, v1 - b1);
                }
            }
            if (MODE == 2) {
#pragma unroll
                for (int i = 0; i < 16; i++)
                    v[i] = 0.5f * v[i] * (1.0f + erff(v[i] * 0.70710678118654752f));
                float* op = outF + (long)row * Ncols + colB + 2 * c4;
#pragma unroll
                for (int nt = 0; nt < 8; nt++) {
                    op[nt * 8 + 0] = v[nt * 2 + 0];
                    op[nt * 8 + 1] = v[nt * 2 + 1];
                }
            }
        }
    }
#undef LOAD_STAGE
}

// ================= gating: smem-cached w2, 16 tokens/block =================
#define GATE_SMEM (64 * 257 * 4 + 4 * 256 * 4 + 4 * 64 * 4)

__global__ __launch_bounds__(256)
void gating_kernel(const float* __restrict__ h1, const float* __restrict__ w2,
                   const float* __restrict__ b2, float* __restrict__ out) {
    extern __shared__ float gs[];
    float* w2s  = gs;                    // [64][257]
    float* hrow = gs + 64 * 257;         // [4][256]
    float* lg   = hrow + 4 * 256;        // [4][64]
    int t = threadIdx.x;
    int grp = t >> 6, e = t & 63;
    for (int i = t; i < 64 * 256; i += 256)
        w2s[(i >> 8) * 257 + (i & 255)] = w2[i];
    __syncthreads();

    for (int rep = 0; rep < 4; rep++) {
        int token = blockIdx.x * 16 + rep * 4 + grp;
        for (int j = e; j < 256; j += 64) hrow[grp * 256 + j] = h1[(long)token * 256 + j];
        __syncthreads();
        float acc = 0.f;
        const float* wr = w2s + e * 257;
        const float* hr = hrow + grp * 256;
#pragma unroll 8
        for (int j = 0; j < 256; j++) acc = fmaf(hr[j], wr[j], acc);
        lg[grp * 64 + e] = acc + b2[e];
        __syncthreads();
        if (e == 0) {
            const float* L = lg + grp * 64;
            int i1 = 0; float v1 = L[0];
            for (int k = 1; k < NEXP; k++) if (L[k] > v1) { v1 = L[k]; i1 = k; }
            int i2 = -1; float v2 = -1e30f;
            for (int k = 0; k < NEXP; k++) if (k != i1 && L[k] > v2) { v2 = L[k]; i2 = k; }
            float s = 0.f;
            for (int k = 0; k < NEXP; k++) s += expf(L[k] - v1);
            float p1 = 1.0f / s;
            float p2 = expf(v2 - v1) / s;
            float wsum = p1 + p2 + 1e-8f;
            out[token * 2 + 0] = (float)i1;
            out[token * 2 + 1] = (float)i2;
            out[NTOK * 2 + token * 2 + 0] = p1 / wsum;
            out[NTOK * 2 + token * 2 + 1] = p2 / wsum;
        }
        __syncthreads();
    }
}

// ================= launch =================
extern "C" void kernel_launch(void* const* d_in, const int* in_sizes, int n_in,
                              void* d_out, int out_size) {
    const float* x   = (const float*)d_in[0];
    const float* emb = (const float*)d_in[1];
    const float* ipw = (const float*)d_in[2];
    const float* ipb = (const float*)d_in[3];
    const float* opw = (const float*)d_in[4];
    const float* opb = (const float*)d_in[5];
    const float* gw1 = (const float*)d_in[6];
    const float* gb1 = (const float*)d_in[7];
    const float* gw2 = (const float*)d_in[8];
    const float* gb2 = (const float*)d_in[9];
    float* out = (float*)d_out;

    float *wkvT, *kv, *c, *W2gT, *c2, *part, *h1, *zero;
    bf16 *MTb, *MTs, *Gtb, *Gts, *xb, *xs, *ab, *as_;
    cudaGetSymbolAddress((void**)&wkvT, g_wkvT);
    cudaGetSymbolAddress((void**)&kv,   g_kv);
    cudaGetSymbolAddress((void**)&c,    g_c);
    cudaGetSymbolAddress((void**)&W2gT, g_W2gT);
    cudaGetSymbolAddress((void**)&c2,   g_c2);
    cudaGetSymbolAddress((void**)&part, g_part);
    cudaGetSymbolAddress((void**)&h1,   g_h1);
    cudaGetSymbolAddress((void**)&zero, g_zero);
    cudaGetSymbolAddress((void**)&MTb,  g_MTb);
    cudaGetSymbolAddress((void**)&MTs,  g_MTs);
    cudaGetSymbolAddress((void**)&Gtb,  g_Gtb);
    cudaGetSymbolAddress((void**)&Gts,  g_Gts);
    cudaGetSymbolAddress((void**)&xb,   g_xb);
    cudaGetSymbolAddress((void**)&xs,   g_xs);
    cudaGetSymbolAddress((void**)&ab,   g_ab);
    cudaGetSymbolAddress((void**)&as_,  g_as);

    cudaFuncSetAttribute(tgemm<1>, cudaFuncAttributeMaxDynamicSharedMemorySize, SMEM_BYTES);
    cudaFuncSetAttribute(tgemm<2>, cudaFuncAttributeMaxDynamicSharedMemorySize, SMEM_BYTES);
    cudaFuncSetAttribute(gating_kernel, cudaFuncAttributeMaxDynamicSharedMemorySize, GATE_SMEM);

    dim3 tb(32, 8);
    // L0: wkv^T
    transpose_kernel<<<dim3(32, 64), tb>>>(ipw + 1024 * 1024, wkvT, 2048, 1024, 1024);
    // L1: split x
    split_x<<<NTOK * DMODEL / 4 / 256, 256>>>((const float4*)x, (uint2*)xb, (uint2*)xs);
    // L2: kv partials (64 x 2048), split-K=8
    sgemm_splitk<<<dim3(16, 1, 8), 256>>>(emb, wkvT, part, 64, 2048);
    // L3: reduce kv (+ k/v bias)
    reduce_splitk<<<(64 * 2048 + 255) / 256, 256>>>(part, ipb + 1024, kv, 64 * 2048, 2048);
    // L4: M^T (split) + c
    build_M_c<<<1024, 256>>>(ipw, ipb, kv, MTb, MTs, c);
    // L5: GEMM1 softmax((x@M + c)/8) -> attn (bf16 split)
    tgemm<1><<<dim3(8, 128), 256, SMEM_BYTES>>>(xb, xs, MTb, MTs, c,
                                                (uint32_t*)ab, (uint32_t*)as_, nullptr, 1024);
    // L6: W2gT partials (256 x 1024), split-K=8
    sgemm_splitk<<<dim3(8, 4, 8), 256>>>(gw1, opw, part, 256, 1024);
    // L7: reduce W2gT
    reduce_splitk<<<(256 * 1024 + 255) / 256, 256>>>(part, zero, W2gT, 256 * 1024, 1024);
    // L8: Gt (split) + c2
    build_Gt<<<256, 256>>>(W2gT, kv, gw1, opb, gb1, Gtb, Gts, c2);
    // L9: GEMM2' h1 = gelu(attn@Gt^T + c2)   (16384 x 256)
    tgemm<2><<<dim3(2, 128), 256, SMEM_BYTES>>>(ab, as_, Gtb, Gts, c2,
                                                nullptr, nullptr, h1, 256);
    // L10: gating
    gating_kernel<<<NTOK / 16, 256, GATE_SMEM>>>(h1, gw2, gb2, out);
    (void)in_sizes; (void)n_in; (void)out_size;
}

// round 9
// speedup vs baseline: 4.7661x; 1.0308x over previous
#include <cuda_runtime.h>
#include <cuda_bf16.h>
#include <math.h>
#include <stdint.h>

#define NTOK   16384
#define DMODEL 1024
#define NEXP   64
#define F1     256

typedef __nv_bfloat16 bf16;

// ================= device scratch =================
__device__ float g_kv  [NEXP * 2 * DMODEL];
__device__ float g_c   [DMODEL];
__device__ float g_W2gT[F1 * DMODEL];
__device__ float g_c2  [F1];
__device__ float g_part [8 * NEXP * 2 * DMODEL];   // kv partials
__device__ float g_part2[8 * F1 * DMODEL];         // W2gT partials
__device__ bf16  g_MTb [DMODEL * DMODEL];
__device__ bf16  g_MTs [DMODEL * DMODEL];
__device__ bf16  g_Gtb [F1 * DMODEL];
__device__ bf16  g_Gts [F1 * DMODEL];
__device__ bf16  g_xb  [NTOK * DMODEL];
__device__ bf16  g_xs  [NTOK * DMODEL];
__device__ bf16  g_ab  [NTOK * DMODEL];
__device__ bf16  g_as  [NTOK * DMODEL];
__device__ float g_h1  [NTOK * F1];
__device__ float g_zero[DMODEL];

// ================= helpers =================
__device__ __forceinline__ uint32_t smem_u32(const void* p) {
    uint32_t a;
    asm("{ .reg .u64 t; cvta.to.shared.u64 t, %1; cvt.u32.u64 %0, t; }" : "=r"(a) : "l"(p));
    return a;
}
__device__ __forceinline__ void cp16(uint32_t dst, const void* src) {
    asm volatile("cp.async.cg.shared.global [%0], [%1], 16;" :: "r"(dst), "l"(src));
}
#define CP_COMMIT() asm volatile("cp.async.commit_group;" ::: "memory")
#define CP_WAIT1()  asm volatile("cp.async.wait_group 1;" ::: "memory")
#define CP_WAIT0()  asm volatile("cp.async.wait_group 0;" ::: "memory")

#define LDSM4(r0, r1, r2, r3, a)                                               \
    asm volatile("ldmatrix.sync.aligned.m8n8.x4.shared.b16 {%0,%1,%2,%3}, [%4];" \
                 : "=r"(r0), "=r"(r1), "=r"(r2), "=r"(r3) : "r"(a))

__device__ __forceinline__ void mma_bf16(float& d0, float& d1, float& d2, float& d3,
                                         uint32_t a0, uint32_t a1, uint32_t a2, uint32_t a3,
                                         uint32_t b0, uint32_t b1) {
    asm volatile(
        "mma.sync.aligned.m16n8k16.row.col.f32.bf16.bf16.f32 "
        "{%0,%1,%2,%3}, {%4,%5,%6,%7}, {%8,%9}, {%0,%1,%2,%3};"
        : "+f"(d0), "+f"(d1), "+f"(d2), "+f"(d3)
        : "r"(a0), "r"(a1), "r"(a2), "r"(a3), "r"(b0), "r"(b1));
}
__device__ __forceinline__ uint32_t pack_bf16(float lo, float hi) {
    uint16_t l = __bfloat16_as_ushort(__float2bfloat16_rn(lo));
    uint16_t h = __bfloat16_as_ushort(__float2bfloat16_rn(hi));
    return (uint32_t)l | ((uint32_t)h << 16);
}

// ================= fp32 -> bf16 split of x =================
__global__ void split_x(const float4* __restrict__ x, uint2* __restrict__ xb,
                        uint2* __restrict__ xs) {
    long i = (long)blockIdx.x * 256 + threadIdx.x;
    float4 v = x[i];
    float bx = __bfloat162float(__float2bfloat16_rn(v.x));
    float by = __bfloat162float(__float2bfloat16_rn(v.y));
    float bz = __bfloat162float(__float2bfloat16_rn(v.z));
    float bw = __bfloat162float(__float2bfloat16_rn(v.w));
    uint2 b, s;
    b.x = pack_bf16(bx, by); b.y = pack_bf16(bz, bw);
    s.x = pack_bf16(v.x - bx, v.y - by);
    s.y = pack_bf16(v.z - bz, v.w - bw);
    xb[i] = b; xs[i] = s;
}

// ================= split-K SIMT SGEMM, B = [k][n] row-major =================
__global__ __launch_bounds__(256)
void sgemm_splitk(const float* __restrict__ A, const float* __restrict__ B,
                  float* __restrict__ P, int Arows, int N) {
    __shared__ float As[8][68];
    __shared__ float Bs[8][128];
    const int t = threadIdx.x;
    const int rowBase = blockIdx.y * 64;
    const int colBase = blockIdx.x * 128;
    const int k0 = blockIdx.z * 128;
    const int m0 = (t >> 4) * 4;
    const int n0 = (t & 15) * 8;
    const int am = t >> 2, akq = (t & 3) * 2;
    const int bn = t & 127, bkb = t >> 7;

    float acc[4][8];
#pragma unroll
    for (int i = 0; i < 4; i++)
#pragma unroll
        for (int j = 0; j < 8; j++) acc[i][j] = 0.f;

    for (int kc = 0; kc < 16; kc++) {
        int kk = k0 + kc * 8;
        float2 av = *(const float2*)(A + (long)(rowBase + am) * 1024 + kk + akq);
        As[akq][am] = av.x; As[akq + 1][am] = av.y;
#pragma unroll
        for (int j = 0; j < 4; j++)
            Bs[bkb + 2 * j][bn] = B[(long)(kk + bkb + 2 * j) * N + colBase + bn];
        __syncthreads();
#pragma unroll
        for (int k = 0; k < 8; k++) {
            float a[4], b[8];
            *(float4*)&a[0] = *(const float4*)&As[k][m0];
            *(float4*)&b[0] = *(const float4*)&Bs[k][n0];
            *(float4*)&b[4] = *(const float4*)&Bs[k][n0 + 4];
#pragma unroll
            for (int i = 0; i < 4; i++)
#pragma unroll
                for (int j = 0; j < 8; j++)
                    acc[i][j] = fmaf(a[i], b[j], acc[i][j]);
        }
        __syncthreads();
    }

    float* Pz = P + (long)blockIdx.z * Arows * N;
#pragma unroll
    for (int i = 0; i < 4; i++) {
        float* op = Pz + (long)(rowBase + m0 + i) * N + colBase + n0;
        *(float4*)op       = make_float4(acc[i][0], acc[i][1], acc[i][2], acc[i][3]);
        *(float4*)(op + 4) = make_float4(acc[i][4], acc[i][5], acc[i][6], acc[i][7]);
    }
}

// ================= split-K SIMT SGEMM, B = [n][k] row-major (A@B^T) =================
__global__ __launch_bounds__(256)
void sgemm_splitk_bt(const float* __restrict__ A, const float* __restrict__ B,
                     float* __restrict__ P, int Arows, int N) {
    __shared__ float As[8][68];
    __shared__ float Bs[8][132];
    const int t = threadIdx.x;
    const int rowBase = blockIdx.y * 64;
    const int colBase = blockIdx.x * 128;
    const int k0 = blockIdx.z * 128;
    const int m0 = (t >> 4) * 4;
    const int n0 = (t & 15) * 8;
    const int am = t >> 2, akq = (t & 3) * 2;
    const int bn = t >> 1, bkq = (t & 1) * 4;

    float acc[4][8];
#pragma unroll
    for (int i = 0; i < 4; i++)
#pragma unroll
        for (int j = 0; j < 8; j++) acc[i][j] = 0.f;

    for (int kc = 0; kc < 16; kc++) {
        int kk = k0 + kc * 8;
        float2 av = *(const float2*)(A + (long)(rowBase + am) * 1024 + kk + akq);
        As[akq][am] = av.x; As[akq + 1][am] = av.y;
        float4 bv = *(const float4*)(B + (long)(colBase + bn) * 1024 + kk + bkq);
        Bs[bkq + 0][bn] = bv.x; Bs[bkq + 1][bn] = bv.y;
        Bs[bkq + 2][bn] = bv.z; Bs[bkq + 3][bn] = bv.w;
        __syncthreads();
#pragma unroll
        for (int k = 0; k < 8; k++) {
            float a[4], b[8];
            *(float4*)&a[0] = *(const float4*)&As[k][m0];
            *(float4*)&b[0] = *(const float4*)&Bs[k][n0];
            *(float4*)&b[4] = *(const float4*)&Bs[k][n0 + 4];
#pragma unroll
            for (int i = 0; i < 4; i++)
#pragma unroll
                for (int j = 0; j < 8; j++)
                    acc[i][j] = fmaf(a[i], b[j], acc[i][j]);
        }
        __syncthreads();
    }

    float* Pz = P + (long)blockIdx.z * Arows * N;
#pragma unroll
    for (int i = 0; i < 4; i++) {
        float* op = Pz + (long)(rowBase + m0 + i) * N + colBase + n0;
        *(float4*)op       = make_float4(acc[i][0], acc[i][1], acc[i][2], acc[i][3]);
        *(float4*)(op + 4) = make_float4(acc[i][4], acc[i][5], acc[i][6], acc[i][7]);
    }
}

__global__ void reduce_splitk(const float* __restrict__ P, const float* __restrict__ bias,
                              float* __restrict__ C, int total, int N) {
    int i = blockIdx.x * 256 + threadIdx.x;
    if (i < total) {
        float s = 0.f;
#pragma unroll
        for (int z = 0; z < 8; z++) s += P[(long)z * total + i];
        C[i] = s + bias[i % N];
    }
}

// ================= build M^T (bf16 split) + c =================
__global__ void build_M_c(const float* __restrict__ ipw, const float* __restrict__ ipb,
                          const float* __restrict__ kv,
                          bf16* __restrict__ MTb, bf16* __restrict__ MTs,
                          float* __restrict__ c) {
    int he = blockIdx.x;
    int h = he >> 6, e = he & 63;
    __shared__ float ke[64];
    int t = threadIdx.x;
    if (t < 64) ke[t] = kv[(long)e * 2048 + h * 64 + t];
    __syncthreads();
    const float* wq = ipw + (long)(h * 64) * 1024;
    for (int d = t; d < 1024; d += 256) {
        float s = 0.f;
#pragma unroll 8
        for (int hd = 0; hd < 64; hd++)
            s = fmaf(wq[(long)hd * 1024 + d], ke[hd], s);
        bf16 b = __float2bfloat16_rn(s);
        MTb[(long)he * 1024 + d] = b;
        MTs[(long)he * 1024 + d] = __float2bfloat16_rn(s - __bfloat162float(b));
    }
    if (t < 32) {
        float s = ke[t] * ipb[h * 64 + t] + ke[t + 32] * ipb[h * 64 + t + 32];
#pragma unroll
        for (int off = 16; off > 0; off >>= 1)
            s += __shfl_xor_sync(0xffffffffu, s, off);
        if (t == 0) c[he] = s;
    }
}

// ================= build Gt (bf16 split) + c2 =================
__global__ void build_Gt(const float* __restrict__ W2gT, const float* __restrict__ kv,
                         const float* __restrict__ gw1, const float* __restrict__ opb,
                         const float* __restrict__ gb1,
                         bf16* __restrict__ Gtb, bf16* __restrict__ Gts,
                         float* __restrict__ c2) {
    int j = blockIdx.x;
    __shared__ float wrow[1024];
    int t = threadIdx.x;
    for (int i = t; i < 1024; i += 256) wrow[i] = W2gT[(long)j * 1024 + i];
    __syncthreads();
    for (int he = t; he < 1024; he += 256) {
        int h = he >> 6, e = he & 63;
        const float* v = kv + (long)e * 2048 + 1024 + h * 64;
        float s = 0.f;
#pragma unroll 8
        for (int hd = 0; hd < 64; hd++)
            s = fmaf(v[hd], wrow[h * 64 + hd], s);
        bf16 b = __float2bfloat16_rn(s);
        Gtb[(long)j * 1024 + he] = b;
        Gts[(long)j * 1024 + he] = __float2bfloat16_rn(s - __bfloat162float(b));
    }
    if (t < 32) {
        float s = 0.f;
        const float* g = gw1 + (long)j * 1024;
        for (int d = t; d < 1024; d += 32) s = fmaf(opb[d], g[d], s);
#pragma unroll
        for (int off = 16; off > 0; off >>= 1)
            s += __shfl_xor_sync(0xffffffffu, s, off);
        if (t == 0) c2[j] = s + gb1[j];
    }
}

// ================= bf16 3-split tensor-core GEMM (ldmatrix + mma.sync) =================
#define ROWW 20
#define TILE_B 10240
#define STAGE_B (4 * TILE_B)
#define SMEM_BYTES (2 * STAGE_B)

template<int MODE>
__global__ __launch_bounds__(256, 2)
void tgemm(const bf16* __restrict__ Ab, const bf16* __restrict__ As,
           const bf16* __restrict__ Bb, const bf16* __restrict__ Bs,
           const float* __restrict__ bias,
           uint32_t* __restrict__ outB, uint32_t* __restrict__ outS,
           float* __restrict__ outF, int Ncols) {
    extern __shared__ uint32_t sm32[];
    uint32_t smu = smem_u32(sm32);

    const int t = threadIdx.x;
    const int w = t >> 5, lane = t & 31;
    const int wm = w >> 1, wn = w & 1;
    const int q = lane >> 2, c4 = lane & 3;

    const int rowBase = blockIdx.y * 128;
    const int colBase = blockIdx.x * 128;

    const int lr = t >> 1;
    const int ls = t & 1;
    const bf16* gAb = Ab + (long)(rowBase + lr) * 1024;
    const bf16* gAs = As + (long)(rowBase + lr) * 1024;
    const bf16* gBb = Bb + (long)(colBase + lr) * 1024;
    const bf16* gBs = Bs + (long)(colBase + lr) * 1024;
    const uint32_t dRow = smu + lr * (ROWW * 4);

    const int lm8 = lane & 7;
    const uint32_t aOff = (uint32_t)(wm * 32 + lm8 + ((lane >> 3) & 1) * 8) * 80
                          + ((lane >> 4) & 1) * 16;
    const uint32_t bOff = (uint32_t)(wn * 64 + lm8 + ((lane >> 4) & 1) * 8) * 80
                          + ((lane >> 3) & 1) * 16;

    float acc[2][8][4];
#pragma unroll
    for (int mt = 0; mt < 2; mt++)
#pragma unroll
        for (int nt = 0; nt < 8; nt++)
#pragma unroll
            for (int i = 0; i < 4; i++) acc[mt][nt][i] = 0.f;

#define LOAD_STAGE(st, ck) do {                                                  \
    int kofs = (ck) * 32;                                                        \
    uint32_t sb = (st) * STAGE_B;                                                \
    _Pragma("unroll")                                                            \
    for (int j = 0; j < 2; j++) {                                                \
        int seg = ls * 2 + j;                                                    \
        cp16(dRow + sb + 0 * TILE_B + seg * 16, gAb + kofs + seg * 8);           \
        cp16(dRow + sb + 1 * TILE_B + seg * 16, gAs + kofs + seg * 8);           \
        cp16(dRow + sb + 2 * TILE_B + seg * 16, gBb + kofs + seg * 8);           \
        cp16(dRow + sb + 3 * TILE_B + seg * 16, gBs + kofs + seg * 8);           \
    }                                                                            \
} while (0)

    LOAD_STAGE(0, 0);
    CP_COMMIT();

    const int NC = 1024 / 32;
    for (int ck = 0; ck < NC; ck++) {
        int buf = ck & 1;
        if (ck + 1 < NC) {
            LOAD_STAGE(buf ^ 1, ck + 1);
            CP_COMMIT();
            CP_WAIT1();
        } else {
            CP_WAIT0();
        }
        __syncthreads();

        const uint32_t s0 = smu + buf * STAGE_B;
        const uint32_t aAb = s0 + aOff;
        const uint32_t aAs = s0 + TILE_B + aOff;
        const uint32_t bBb = s0 + 2 * TILE_B + bOff;
        const uint32_t bBs = s0 + 3 * TILE_B + bOff;

#pragma unroll
        for (int ks = 0; ks < 2; ks++) {
            uint32_t fab[2][4], fas[2][4];
            LDSM4(fab[0][0], fab[0][1], fab[0][2], fab[0][3], aAb + ks * 32);
            LDSM4(fab[1][0], fab[1][1], fab[1][2], fab[1][3], aAb + 1280 + ks * 32);
            LDSM4(fas[0][0], fas[0][1], fas[0][2], fas[0][3], aAs + ks * 32);
            LDSM4(fas[1][0], fas[1][1], fas[1][2], fas[1][3], aAs + 1280 + ks * 32);
#pragma unroll
            for (int jh = 0; jh < 2; jh++) {
                uint32_t fbb[4][2], fbs[4][2];
                LDSM4(fbb[0][0], fbb[0][1], fbb[1][0], fbb[1][1],
                      bBb + (2 * jh) * 1280 + ks * 32);
                LDSM4(fbb[2][0], fbb[2][1], fbb[3][0], fbb[3][1],
                      bBb + (2 * jh + 1) * 1280 + ks * 32);
                LDSM4(fbs[0][0], fbs[0][1], fbs[1][0], fbs[1][1],
                      bBs + (2 * jh) * 1280 + ks * 32);
                LDSM4(fbs[2][0], fbs[2][1], fbs[3][0], fbs[3][1],
                      bBs + (2 * jh + 1) * 1280 + ks * 32);
#pragma unroll
                for (int l = 0; l < 4; l++)
#pragma unroll
                    for (int mt = 0; mt < 2; mt++) {
                        float* d = acc[mt][4 * jh + l];
                        mma_bf16(d[0], d[1], d[2], d[3],
                                 fab[mt][0], fab[mt][1], fab[mt][2], fab[mt][3],
                                 fbb[l][0], fbb[l][1]);
                    }
#pragma unroll
                for (int l = 0; l < 4; l++)
#pragma unroll
                    for (int mt = 0; mt < 2; mt++) {
                        float* d = acc[mt][4 * jh + l];
                        mma_bf16(d[0], d[1], d[2], d[3],
                                 fab[mt][0], fab[mt][1], fab[mt][2], fab[mt][3],
                                 fbs[l][0], fbs[l][1]);
                    }
#pragma unroll
                for (int l = 0; l < 4; l++)
#pragma unroll
                    for (int mt = 0; mt < 2; mt++) {
                        float* d = acc[mt][4 * jh + l];
                        mma_bf16(d[0], d[1], d[2], d[3],
                                 fas[mt][0], fas[mt][1], fas[mt][2], fas[mt][3],
                                 fbb[l][0], fbb[l][1]);
                    }
            }
        }
        __syncthreads();
    }

    const int colB = colBase + wn * 64;
    float bv[16];
#pragma unroll
    for (int nt = 0; nt < 8; nt++) {
#pragma unroll
        for (int j = 0; j < 2; j++)
            bv[nt * 2 + j] = bias[colB + nt * 8 + 2 * c4 + j];
    }

#pragma unroll
    for (int mt = 0; mt < 2; mt++) {
#pragma unroll
        for (int h = 0; h < 2; h++) {
            int row = rowBase + wm * 32 + mt * 16 + q + h * 8;
            float v[16];
#pragma unroll
            for (int nt = 0; nt < 8; nt++) {
                v[nt * 2 + 0] = acc[mt][nt][2 * h + 0] + bv[nt * 2 + 0];
                v[nt * 2 + 1] = acc[mt][nt][2 * h + 1] + bv[nt * 2 + 1];
            }
            if (MODE == 1) {
#pragma unroll
                for (int i = 0; i < 16; i++) v[i] *= 0.125f;
                float m = v[0];
#pragma unroll
                for (int i = 1; i < 16; i++) m = fmaxf(m, v[i]);
                m = fmaxf(m, __shfl_xor_sync(0xffffffffu, m, 1));
                m = fmaxf(m, __shfl_xor_sync(0xffffffffu, m, 2));
                float s = 0.f;
#pragma unroll
                for (int i = 0; i < 16; i++) { v[i] = expf(v[i] - m); s += v[i]; }
                s += __shfl_xor_sync(0xffffffffu, s, 1);
                s += __shfl_xor_sync(0xffffffffu, s, 2);
                float inv = 1.f / s;
#pragma unroll
                for (int i = 0; i < 16; i++) v[i] *= inv;
                uint32_t* ob = outB + (long)row * (Ncols / 2) + (colB >> 1) + c4;
                uint32_t* os = outS + (long)row * (Ncols / 2) + (colB >> 1) + c4;
#pragma unroll
                for (int nt = 0; nt < 8; nt++) {
                    float v0 = v[nt * 2], v1 = v[nt * 2 + 1];
                    float b0 = __bfloat162float(__float2bfloat16_rn(v0));
                    float b1 = __bfloat162float(__float2bfloat16_rn(v1));
                    ob[nt * 4] = pack_bf16(b0, b1);
                    os[nt * 4] = pack_bf16(v0 - b0, v1 - b1);
                }
            }
            if (MODE == 2) {
#pragma unroll
                for (int i = 0; i < 16; i++)
                    v[i] = 0.5f * v[i] * (1.0f + erff(v[i] * 0.70710678118654752f));
                float* op = outF + (long)row * Ncols + colB + 2 * c4;
#pragma unroll
                for (int nt = 0; nt < 8; nt++) {
                    op[nt * 8 + 0] = v[nt * 2 + 0];
                    op[nt * 8 + 1] = v[nt * 2 + 1];
                }
            }
        }
    }
#undef LOAD_STAGE
}

// ================= gating: smem-cached w2, 16 tokens/block =================
#define GATE_SMEM (64 * 257 * 4 + 4 * 256 * 4 + 4 * 64 * 4)

__global__ __launch_bounds__(256)
void gating_kernel(const float* __restrict__ h1, const float* __restrict__ w2,
                   const float* __restrict__ b2, float* __restrict__ out) {
    extern __shared__ float gs[];
    float* w2s  = gs;
    float* hrow = gs + 64 * 257;
    float* lg   = hrow + 4 * 256;
    int t = threadIdx.x;
    int grp = t >> 6, e = t & 63;
    for (int i = t; i < 64 * 256; i += 256)
        w2s[(i >> 8) * 257 + (i & 255)] = w2[i];
    __syncthreads();

    for (int rep = 0; rep < 4; rep++) {
        int token = blockIdx.x * 16 + rep * 4 + grp;
        for (int j = e; j < 256; j += 64) hrow[grp * 256 + j] = h1[(long)token * 256 + j];
        __syncthreads();
        float acc = 0.f;
        const float* wr = w2s + e * 257;
        const float* hr = hrow + grp * 256;
#pragma unroll 8
        for (int j = 0; j < 256; j++) acc = fmaf(hr[j], wr[j], acc);
        lg[grp * 64 + e] = acc + b2[e];
        __syncthreads();
        if (e == 0) {
            const float* L = lg + grp * 64;
            int i1 = 0; float v1 = L[0];
            for (int k = 1; k < NEXP; k++) if (L[k] > v1) { v1 = L[k]; i1 = k; }
            int i2 = -1; float v2 = -1e30f;
            for (int k = 0; k < NEXP; k++) if (k != i1 && L[k] > v2) { v2 = L[k]; i2 = k; }
            float s = 0.f;
            for (int k = 0; k < NEXP; k++) s += expf(L[k] - v1);
            float p1 = 1.0f / s;
            float p2 = expf(v2 - v1) / s;
            float wsum = p1 + p2 + 1e-8f;
            out[token * 2 + 0] = (float)i1;
            out[token * 2 + 1] = (float)i2;
            out[NTOK * 2 + token * 2 + 0] = p1 / wsum;
            out[NTOK * 2 + token * 2 + 1] = p2 / wsum;
        }
        __syncthreads();
    }
}

// ================= launch =================
extern "C" void kernel_launch(void* const* d_in, const int* in_sizes, int n_in,
                              void* d_out, int out_size) {
    const float* x   = (const float*)d_in[0];
    const float* emb = (const float*)d_in[1];
    const float* ipw = (const float*)d_in[2];
    const float* ipb = (const float*)d_in[3];
    const float* opw = (const float*)d_in[4];
    const float* opb = (const float*)d_in[5];
    const float* gw1 = (const float*)d_in[6];
    const float* gb1 = (const float*)d_in[7];
    const float* gw2 = (const float*)d_in[8];
    const float* gb2 = (const float*)d_in[9];
    float* out = (float*)d_out;

    float *kv, *c, *W2gT, *c2, *part, *part2, *h1, *zero;
    bf16 *MTb, *MTs, *Gtb, *Gts, *xb, *xs, *ab, *as_;
    cudaGetSymbolAddress((void**)&kv,    g_kv);
    cudaGetSymbolAddress((void**)&c,     g_c);
    cudaGetSymbolAddress((void**)&W2gT,  g_W2gT);
    cudaGetSymbolAddress((void**)&c2,    g_c2);
    cudaGetSymbolAddress((void**)&part,  g_part);
    cudaGetSymbolAddress((void**)&part2, g_part2);
    cudaGetSymbolAddress((void**)&h1,    g_h1);
    cudaGetSymbolAddress((void**)&zero,  g_zero);
    cudaGetSymbolAddress((void**)&MTb,   g_MTb);
    cudaGetSymbolAddress((void**)&MTs,   g_MTs);
    cudaGetSymbolAddress((void**)&Gtb,   g_Gtb);
    cudaGetSymbolAddress((void**)&Gts,   g_Gts);
    cudaGetSymbolAddress((void**)&xb,    g_xb);
    cudaGetSymbolAddress((void**)&xs,    g_xs);
    cudaGetSymbolAddress((void**)&ab,    g_ab);
    cudaGetSymbolAddress((void**)&as_,   g_as);

    // one-time resource init (first call is the non-captured correctness run)
    static cudaStream_t s1 = nullptr, s2 = nullptr;
    static cudaEvent_t evRoot = nullptr, evSplit = nullptr, evKv = nullptr, evGt = nullptr;
    if (s1 == nullptr) {
        cudaStreamCreateWithFlags(&s1, cudaStreamNonBlocking);
        cudaStreamCreateWithFlags(&s2, cudaStreamNonBlocking);
        cudaEventCreateWithFlags(&evRoot,  cudaEventDisableTiming);
        cudaEventCreateWithFlags(&evSplit, cudaEventDisableTiming);
        cudaEventCreateWithFlags(&evKv,    cudaEventDisableTiming);
        cudaEventCreateWithFlags(&evGt,    cudaEventDisableTiming);
        cudaFuncSetAttribute(tgemm<1>, cudaFuncAttributeMaxDynamicSharedMemorySize, SMEM_BYTES);
        cudaFuncSetAttribute(tgemm<2>, cudaFuncAttributeMaxDynamicSharedMemorySize, SMEM_BYTES);
        cudaFuncSetAttribute(gating_kernel, cudaFuncAttributeMaxDynamicSharedMemorySize, GATE_SMEM);
    }

    // fork
    cudaEventRecord(evRoot, 0);
    cudaStreamWaitEvent(s1, evRoot, 0);
    cudaStreamWaitEvent(s2, evRoot, 0);

    // s1: split x (input to GEMM1)
    split_x<<<NTOK * DMODEL / 4 / 256, 256, 0, s1>>>((const float4*)x, (uint2*)xb, (uint2*)xs);
    cudaEventRecord(evSplit, s1);

    // s2: W2gT chain (independent of kv until build_Gt)
    sgemm_splitk<<<dim3(8, 4, 8), 256, 0, s2>>>(gw1, opw, part2, 256, 1024);
    reduce_splitk<<<(256 * 1024 + 255) / 256, 256, 0, s2>>>(part2, zero, W2gT, 256 * 1024, 1024);

    // s0: kv chain (critical path)
    sgemm_splitk_bt<<<dim3(16, 1, 8), 256>>>(emb, ipw + 1024 * 1024, part, 64, 2048);
    reduce_splitk<<<(64 * 2048 + 255) / 256, 256>>>(part, ipb + 1024, kv, 64 * 2048, 2048);
    cudaEventRecord(evKv, 0);

    // s2: build_Gt needs kv (v half) + W2gT
    cudaStreamWaitEvent(s2, evKv, 0);
    build_Gt<<<256, 256, 0, s2>>>(W2gT, kv, gw1, opb, gb1, Gtb, Gts, c2);
    cudaEventRecord(evGt, s2);

    // s0: M builder + main GEMMs
    build_M_c<<<1024, 256>>>(ipw, ipb, kv, MTb, MTs, c);
    cudaStreamWaitEvent(0, evSplit, 0);
    tgemm<1><<<dim3(8, 128), 256, SMEM_BYTES>>>(xb, xs, MTb, MTs, c,
                                                (uint32_t*)ab, (uint32_t*)as_, nullptr, 1024);
    cudaStreamWaitEvent(0, evGt, 0);
    tgemm<2><<<dim3(2, 128), 256, SMEM_BYTES>>>(ab, as_, Gtb, Gts, c2,
                                                nullptr, nullptr, h1, 256);
    gating_kernel<<<NTOK / 16, 256, GATE_SMEM>>>(h1, gw2, gb2, out);
    (void)in_sizes; (void)n_in; (void)out_size;
}